// round 2
// baseline (speedup 1.0000x reference)
#include <cuda_runtime.h>
#include <math.h>

#define Bn 8
#define Sn 256
#define TIN 10
#define WID 32
#define C0c 33
#define NT 24
#define NJ 48
#define NM 576

// -------- scratch (device globals; no allocation allowed) --------
__device__ float g_h0[(size_t)Bn*C0c*Sn*Sn];   // 69 MB (33-ch buffer)
__device__ float g_h1[(size_t)Bn*WID*Sn*Sn];   // 67 MB (32-ch buffer)
__device__ float g_T [(size_t)Bn*C0c*Sn*NJ];   // 13 MB
__device__ float g_X [(size_t)Bn*C0c*NM*2];
__device__ float g_OF[(size_t)Bn*WID*NM*2];
__device__ float g_G [(size_t)Bn*WID*Sn*NJ];
__device__ float g_wmix[(size_t)4*144*C0c*WID*2];
__device__ float g_TFx[Sn*NJ];
__device__ float g_TFy[Sn*NJ];
__device__ float g_TGy[Sn*NJ];
__device__ float g_TWx[Sn*NJ];

// -------- twiddle tables (exact via double sincospi) --------
__global__ void k_init() {
    int v = blockIdx.x; int j = threadIdx.x; int t = j >> 1; int im = j & 1;
    int kx = t < 12 ? t : 105 + t;   // 0..11, 117..128
    int ky = t < 12 ? t : 232 + t;   // 0..11, 244..255
    double s, c;
    // forward x: e^{-i 2pi kx v/256} -> (cos, -sin)
    sincospi(2.0 * kx * v / 256.0, &s, &c);
    g_TFx[v*NJ + j] = im ? (float)(-s) : (float)c;
    // inverse x (c2r): norm 1/65536, factor 2 for 1..127, imag dropped at kx=0,128
    const double inv = 1.0 / 65536.0;
    double ar, bi;
    if (kx == 0)        { ar = inv;        bi = 0.0; }
    else if (kx == 128) { ar = c * inv;    bi = 0.0; }
    else                { ar = 2.0*c*inv;  bi = -2.0*s*inv; }
    g_TWx[v*NJ + j] = im ? (float)bi : (float)ar;
    // forward y: e^{-i theta}; inverse y: e^{+i theta}
    sincospi(2.0 * ky * v / 256.0, &s, &c);
    g_TFy[v*NJ + j] = im ? (float)(-s) : (float)c;
    g_TGy[v*NJ + j] = im ? (float)s    : (float)c;
}

// -------- fc0 + grid concat + a_para concat + *a, to NCHW --------
__global__ void k_fc0(const float* __restrict__ x, const float* __restrict__ ap,
                      const float* __restrict__ w, const float* __restrict__ bias) {
    __shared__ float sw[12*32];
    __shared__ float sb[32];
    int tid = threadIdx.x;
    for (int i = tid; i < 384; i += 256) sw[i] = w[i];   // FIXED: was `if (tid<384)` with 256 threads
    if (tid < 32)  sb[tid] = bias[tid];
    __syncthreads();
    int u = blockIdx.x, b = blockIdx.y, v = tid;
    const float* xp = x + (((size_t)b*Sn + u)*Sn + v)*TIN;
    float in[12];
    #pragma unroll
    for (int t = 0; t < 10; t++) in[t] = xp[t];
    in[10] = u * (1.0f/255.0f);
    in[11] = v * (1.0f/255.0f);
    float a = ap[((size_t)b*Sn + u)*Sn + v];
    float* hp = g_h0 + (size_t)b*C0c*Sn*Sn + (size_t)u*Sn + v;
    #pragma unroll 4
    for (int c = 0; c < 32; c++) {
        float acc = sb[c];
        #pragma unroll
        for (int t = 0; t < 12; t++) acc += in[t]*sw[t*32 + c];
        hp[(size_t)c*Sn*Sn] = acc * a;
    }
    hp[(size_t)32*Sn*Sn] = a * a;   // a_para channel, times a
}

// -------- repack rainbow weights: [4,Ci,Co,12,12,2] -> [q][m][ci][co][2] --------
__global__ void k_wprep(const float* __restrict__ rb, int Cin) {
    int total = 4*144*Cin*WID*2;
    for (int i = blockIdx.x*blockDim.x + threadIdx.x; i < total; i += gridDim.x*blockDim.x) {
        int r = i & 1; int tmp = i >> 1;
        int co = tmp % WID; tmp /= WID;
        int ci = tmp % Cin; tmp /= Cin;
        int m = tmp % 144;  int q = tmp / 144;
        int m1 = m / 12, m2 = m % 12;
        g_wmix[i] = rb[((((size_t)(q*Cin + ci)*WID + co)*12 + m1)*12 + m2)*2 + r];
    }
}

// -------- forward stage 1: T = h @ TFx  (Mx256 @ 256x48) --------
__global__ void k_f1(const float* __restrict__ src) {
    extern __shared__ float sm[];
    float* sA = sm;              // 64 x 257
    float* sB = sm + 64*257;     // 256 x 48
    int tid = threadIdx.x;
    size_t rowbase = (size_t)blockIdx.x * 64;
    for (int i = tid; i < 64*256; i += 256) {
        int r = i >> 8, k = i & 255;
        sA[r*257 + k] = src[(rowbase + r)*256 + k];
    }
    for (int i = tid; i < Sn*NJ; i += 256) sB[i] = g_TFx[i];
    __syncthreads();
    int tx = tid & 15, ty = tid >> 4;
    int j0 = tx*3, r0 = ty*4;
    float acc[4][3] = {};
    #pragma unroll 4
    for (int k = 0; k < 256; k++) {
        float b0 = sB[k*NJ + j0], b1 = sB[k*NJ + j0 + 1], b2 = sB[k*NJ + j0 + 2];
        #pragma unroll
        for (int i = 0; i < 4; i++) {
            float a = sA[(r0 + i)*257 + k];
            acc[i][0] += a*b0; acc[i][1] += a*b1; acc[i][2] += a*b2;
        }
    }
    #pragma unroll
    for (int i = 0; i < 4; i++)
        #pragma unroll
        for (int q = 0; q < 3; q++)
            g_T[(rowbase + r0 + i)*NJ + j0 + q] = acc[i][q];
}

// -------- forward stage 2: X[t,s] = sum_u e^{-i th_y} T[u,s] --------
__global__ void k_f2() {
    extern __shared__ float sm[];
    float* sT  = sm;           // 12288
    float* sFy = sm + 12288;   // 12288
    int tid = threadIdx.y*24 + threadIdx.x;
    size_t bc = blockIdx.x;
    const float* Tp = g_T + bc*Sn*NJ;
    for (int i = tid; i < Sn*NJ; i += 576) { sT[i] = Tp[i]; sFy[i] = g_TFy[i]; }
    __syncthreads();
    int t = threadIdx.y, s = threadIdx.x;
    float xr = 0.f, xi = 0.f;
    for (int u = 0; u < 256; u++) {
        float A = sFy[u*NJ + 2*t], Bv = sFy[u*NJ + 2*t + 1];
        float tr = sT[u*NJ + 2*s], ti = sT[u*NJ + 2*s + 1];
        xr += A*tr - Bv*ti;
        xi += A*ti + Bv*tr;
    }
    g_X[(bc*NM + t*24 + s)*2]     = xr;
    g_X[(bc*NM + t*24 + s)*2 + 1] = xi;
}

// -------- per-mode complex channel mixing --------
__global__ void k_mix(int Cin) {
    __shared__ float sx[C0c*2];
    int mode = blockIdx.x; int b = blockIdx.y;
    int t = mode / 24, s = mode % 24;
    int q = (t >= 12 ? 1 : 0) + (s >= 12 ? 2 : 0);
    int m = (t % 12)*12 + (s % 12);
    int co = threadIdx.x;
    for (int i = co; i < Cin*2; i += 32)
        sx[i] = g_X[(((size_t)b*Cin + (i >> 1))*NM + mode)*2 + (i & 1)];
    __syncthreads();
    const float2* wp = (const float2*)g_wmix + (size_t)(q*144 + m)*Cin*WID;
    float orr = 0.f, oi = 0.f;
    for (int ci = 0; ci < Cin; ci++) {
        float2 w = wp[ci*WID + co];
        float xr = sx[2*ci], xi = sx[2*ci + 1];
        orr += xr*w.x - xi*w.y;
        oi  += xr*w.y + xi*w.x;
    }
    g_OF[(((size_t)b*WID + co)*NM + mode)*2]     = orr;
    g_OF[(((size_t)b*WID + co)*NM + mode)*2 + 1] = oi;
}

// -------- inverse stage 1: ky-iDFT (24 -> 256 rows), complex --------
__global__ void k_i1() {
    extern __shared__ float sm[];
    float* sOF = sm;            // 1152
    float* sGy = sm + 1152;     // 256 x 49 (padded)
    int tid = threadIdx.x;
    size_t bc = blockIdx.x;     // b*32 + co
    for (int i = tid; i < NM*2; i += 256) sOF[i] = g_OF[bc*NM*2 + i];
    for (int i = tid; i < Sn*NJ; i += 256) {
        int u = i / NJ, j = i % NJ;
        sGy[u*49 + j] = g_TGy[i];
    }
    __syncthreads();
    int u = tid;
    float* gp = g_G + (bc*Sn + u)*NJ;
    const float* grow = sGy + u*49;
    for (int s = 0; s < 24; s++) {
        float gr = 0.f, gi = 0.f;
        #pragma unroll
        for (int t = 0; t < 24; t++) {
            float C = grow[2*t], S = grow[2*t + 1];
            float ofr = sOF[(t*24 + s)*2], ofi = sOF[(t*24 + s)*2 + 1];
            gr += C*ofr - S*ofi;
            gi += C*ofi + S*ofr;
        }
        gp[2*s] = gr; gp[2*s + 1] = gi;
    }
}

// -------- inverse stage 2 + 1x1 conv + bias + (gelu) --------
template<int CIN, bool DOGELU>
__global__ void k_i2(const float* __restrict__ src, float* __restrict__ dst,
                     const float* __restrict__ cw, const float* __restrict__ cb) {
    extern __shared__ float sm[];
    float* sWx = sm;               // 256*49 padded
    float* sG  = sm + 256*49;      // 32*48
    float* scw = sG + 32*NJ;       // 32*CIN
    float* scb = scw + 32*CIN;     // 32
    int tid = threadIdx.x;
    int u = blockIdx.x, b = blockIdx.y;
    for (int i = tid; i < Sn*NJ; i += 256) {
        int v = i / NJ, j = i % NJ;
        sWx[v*49 + j] = g_TWx[i];
    }
    for (int i = tid; i < 32*NJ; i += 256) {
        int co = i / NJ, j = i % NJ;
        sG[i] = g_G[((((size_t)b*WID + co)*Sn) + u)*NJ + j];
    }
    for (int i = tid; i < 32*CIN; i += 256) scw[i] = cw[i];
    if (tid < 32) scb[tid] = cb[tid];
    __syncthreads();
    int v = tid;
    float r[CIN];
    #pragma unroll
    for (int ci = 0; ci < CIN; ci++)
        r[ci] = src[(((size_t)b*CIN + ci)*Sn + u)*Sn + v];
    const float* wrow = sWx + v*49;
    #pragma unroll 1
    for (int co = 0; co < 32; co++) {
        float acc = scb[co];
        const float* gg = sG + co*NJ;
        #pragma unroll
        for (int j = 0; j < NJ; j++) acc += gg[j]*wrow[j];
        #pragma unroll
        for (int ci = 0; ci < CIN; ci++) acc += r[ci]*scw[co*CIN + ci];
        if (DOGELU) acc = 0.5f*acc*(1.0f + erff(acc*0.70710678118654752f));
        dst[(((size_t)b*WID + co)*Sn + u)*Sn + v] = acc;
    }
}

// -------- fused fc1 + gelu + fc2 --------
__global__ void k_fc12(const float* __restrict__ w1, const float* __restrict__ b1,
                       const float* __restrict__ w2, const float* __restrict__ b2,
                       float* __restrict__ out) {
    __shared__ float sW1[32*128];
    __shared__ float sW2[128];
    __shared__ float sB1[128];
    int tid = threadIdx.x;
    for (int i = tid; i < 4096; i += 256) sW1[i] = w1[i];
    if (tid < 128) { sW2[tid] = w2[tid]; sB1[tid] = b1[tid]; }
    __syncthreads();
    int u = blockIdx.x, b = blockIdx.y, v = tid;
    float hv[32];
    #pragma unroll
    for (int c = 0; c < 32; c++)
        hv[c] = g_h0[(((size_t)b*WID + c)*Sn + u)*Sn + v];
    float o = b2[0];
    #pragma unroll 2
    for (int k = 0; k < 128; k++) {
        float z = sB1[k];
        #pragma unroll
        for (int c = 0; c < 32; c++) z += hv[c]*sW1[c*128 + k];
        z = 0.5f*z*(1.0f + erff(z*0.70710678118654752f));
        o += z*sW2[k];
    }
    out[((size_t)b*Sn + u)*Sn + v] = o;
}

// -------- host --------
#define SM_F1 ((64*257 + 256*48)*4)
#define SM_F2 (2*256*48*4)
#define SM_I1 ((1152 + 256*49)*4)
#define SM_I2(CIN) ((256*49 + 32*48 + 32*(CIN) + 32)*4)

extern "C" void kernel_launch(void* const* d_in, const int* in_sizes, int n_in,
                              void* d_out, int out_size) {
    const float* x    = (const float*)d_in[0];
    const float* ap   = (const float*)d_in[1];
    const float* fc0w = (const float*)d_in[2];
    const float* fc0b = (const float*)d_in[3];
    const float* rb[4] = {(const float*)d_in[4], (const float*)d_in[5],
                          (const float*)d_in[6], (const float*)d_in[7]};
    const float* cw[4] = {(const float*)d_in[8],  (const float*)d_in[10],
                          (const float*)d_in[12], (const float*)d_in[14]};
    const float* cb[4] = {(const float*)d_in[9],  (const float*)d_in[11],
                          (const float*)d_in[13], (const float*)d_in[15]};
    const float* fc1w = (const float*)d_in[16];
    const float* fc1b = (const float*)d_in[17];
    const float* fc2w = (const float*)d_in[18];
    const float* fc2b = (const float*)d_in[19];
    float* out = (float*)d_out;

    float *h0, *h1;
    cudaGetSymbolAddress((void**)&h0, g_h0);
    cudaGetSymbolAddress((void**)&h1, g_h1);

    cudaFuncSetAttribute(k_f1, cudaFuncAttributeMaxDynamicSharedMemorySize, SM_F1);
    cudaFuncSetAttribute(k_f2, cudaFuncAttributeMaxDynamicSharedMemorySize, SM_F2);
    cudaFuncSetAttribute(k_i1, cudaFuncAttributeMaxDynamicSharedMemorySize, SM_I1);
    cudaFuncSetAttribute(k_i2<33,true>,  cudaFuncAttributeMaxDynamicSharedMemorySize, SM_I2(33));
    cudaFuncSetAttribute(k_i2<32,true>,  cudaFuncAttributeMaxDynamicSharedMemorySize, SM_I2(32));
    cudaFuncSetAttribute(k_i2<32,false>, cudaFuncAttributeMaxDynamicSharedMemorySize, SM_I2(32));

    k_init<<<256, 48>>>();
    k_fc0<<<dim3(Sn, Bn), 256>>>(x, ap, fc0w, fc0b);

    float* bufs[5] = {h0, h1, h0, h1, h0};
    for (int blk = 0; blk < 4; blk++) {
        int Cin = (blk == 0) ? 33 : 32;
        k_wprep<<<1024, 256>>>(rb[blk], Cin);
        int nrows = Bn*Cin*Sn;
        k_f1<<<nrows/64, 256, SM_F1>>>(bufs[blk]);
        k_f2<<<Bn*Cin, dim3(24, 24), SM_F2>>>();
        k_mix<<<dim3(NM, Bn), 32>>>(Cin);
        k_i1<<<Bn*WID, 256, SM_I1>>>();
        if (blk == 0)
            k_i2<33,true><<<dim3(Sn, Bn), 256, SM_I2(33)>>>(bufs[0], bufs[1], cw[0], cb[0]);
        else if (blk < 3)
            k_i2<32,true><<<dim3(Sn, Bn), 256, SM_I2(32)>>>(bufs[blk], bufs[blk+1], cw[blk], cb[blk]);
        else
            k_i2<32,false><<<dim3(Sn, Bn), 256, SM_I2(32)>>>(bufs[3], bufs[4], cw[3], cb[3]);
    }
    k_fc12<<<dim3(Sn, Bn), 256>>>(fc1w, fc1b, fc2w, fc2b, out);
}

// round 4
// speedup vs baseline: 1.1456x; 1.1456x over previous
#include <cuda_runtime.h>
#include <math.h>

#define Bn 8
#define Sn 256
#define TIN 10
#define WID 32
#define C0c 33
#define NT 24
#define NJ 48
#define NM 576

// -------- scratch (device globals; no allocation allowed) --------
__device__ float g_h0[(size_t)Bn*C0c*Sn*Sn];   // 69 MB (33-ch buffer)
__device__ float g_h1[(size_t)Bn*WID*Sn*Sn];   // 67 MB (32-ch buffer)
__device__ float g_T [(size_t)Bn*C0c*Sn*NJ];   // 13 MB
__device__ float g_X [(size_t)Bn*C0c*NM*2];
__device__ float g_OF[(size_t)Bn*WID*NM*2];
__device__ float g_G [(size_t)Bn*WID*Sn*NJ];
__device__ float g_wmix[(size_t)4*144*C0c*WID*2];
__device__ float g_TFx[Sn*NJ];
__device__ float g_TFy[Sn*NJ];
__device__ float g_TGy[Sn*NJ];
__device__ float g_TWx[Sn*NJ];

// -------- twiddle tables (exact via double sincospi) --------
__global__ void k_init() {
    int v = blockIdx.x; int j = threadIdx.x; int t = j >> 1; int im = j & 1;
    int kx = t < 12 ? t : 105 + t;   // 0..11, 117..128
    int ky = t < 12 ? t : 232 + t;   // 0..11, 244..255
    double s, c;
    sincospi(2.0 * kx * v / 256.0, &s, &c);
    g_TFx[v*NJ + j] = im ? (float)(-s) : (float)c;
    const double inv = 1.0 / 65536.0;
    double ar, bi;
    if (kx == 0)        { ar = inv;        bi = 0.0; }
    else if (kx == 128) { ar = c * inv;    bi = 0.0; }
    else                { ar = 2.0*c*inv;  bi = -2.0*s*inv; }
    g_TWx[v*NJ + j] = im ? (float)bi : (float)ar;
    sincospi(2.0 * ky * v / 256.0, &s, &c);
    g_TFy[v*NJ + j] = im ? (float)(-s) : (float)c;
    g_TGy[v*NJ + j] = im ? (float)s    : (float)c;
}

// -------- fc0 + grid concat + a_para concat + *a, to NCHW --------
__global__ void k_fc0(const float* __restrict__ x, const float* __restrict__ ap,
                      const float* __restrict__ w, const float* __restrict__ bias) {
    __shared__ float sw[12*32];
    __shared__ float sb[32];
    int tid = threadIdx.x;
    for (int i = tid; i < 384; i += 256) sw[i] = w[i];
    if (tid < 32)  sb[tid] = bias[tid];
    __syncthreads();
    int u = blockIdx.x, b = blockIdx.y, v = tid;
    const float* xp = x + (((size_t)b*Sn + u)*Sn + v)*TIN;
    float in[12];
    #pragma unroll
    for (int t = 0; t < 10; t++) in[t] = xp[t];
    in[10] = u * (1.0f/255.0f);
    in[11] = v * (1.0f/255.0f);
    float a = ap[((size_t)b*Sn + u)*Sn + v];
    float* hp = g_h0 + (size_t)b*C0c*Sn*Sn + (size_t)u*Sn + v;
    #pragma unroll 4
    for (int c = 0; c < 32; c++) {
        float acc = sb[c];
        #pragma unroll
        for (int t = 0; t < 12; t++) acc += in[t]*sw[t*32 + c];
        hp[(size_t)c*Sn*Sn] = acc * a;
    }
    hp[(size_t)32*Sn*Sn] = a * a;
}

// -------- repack rainbow weights: [4,Ci,Co,12,12,2] -> [q][m][ci][co][2] --------
__global__ void k_wprep(const float* __restrict__ rb, int Cin) {
    int total = 4*144*Cin*WID*2;
    for (int i = blockIdx.x*blockDim.x + threadIdx.x; i < total; i += gridDim.x*blockDim.x) {
        int r = i & 1; int tmp = i >> 1;
        int co = tmp % WID; tmp /= WID;
        int ci = tmp % Cin; tmp /= Cin;
        int m = tmp % 144;  int q = tmp / 144;
        int m1 = m / 12, m2 = m % 12;
        g_wmix[i] = rb[((((size_t)(q*Cin + ci)*WID + co)*12 + m1)*12 + m2)*2 + r];
    }
}

// -------- forward stage 1: T = h @ TFx  (128x256 @ 256x48 per block) --------
#define F1_ROWS 128
#define F1_PAD 260
#define SM_F1 ((F1_ROWS*F1_PAD + 256*48)*4)
__global__ __launch_bounds__(512) void k_f1(const float* __restrict__ src) {
    extern __shared__ float sm[];
    float* sA = sm;                    // 128 x 260 (row-major, padded, f4-aligned)
    float* sB = sm + F1_ROWS*F1_PAD;   // 256 x 48
    int tid = threadIdx.x;
    size_t rowbase = (size_t)blockIdx.x * F1_ROWS;
    for (int i = tid; i < F1_ROWS*64; i += 512) {
        int r = i >> 6, k4 = i & 63;
        float4 vv = ((const float4*)(src + (rowbase + r)*256))[k4];
        *((float4*)(sA + r*F1_PAD + k4*4)) = vv;
    }
    for (int i = tid; i < 256*48/4; i += 512)
        ((float4*)sB)[i] = ((const float4*)g_TFx)[i];
    __syncthreads();
    int tx = tid & 15, ty = tid >> 4;   // tx 0..15 (3 cols), ty 0..31 (4 rows)
    int j0 = tx*3, r0 = ty*4;
    float acc[4][3] = {};
    #pragma unroll 4
    for (int k = 0; k < 256; k++) {
        float b0 = sB[k*NJ + j0], b1 = sB[k*NJ + j0 + 1], b2 = sB[k*NJ + j0 + 2];
        #pragma unroll
        for (int i = 0; i < 4; i++) {
            float a = sA[(r0 + i)*F1_PAD + k];
            acc[i][0] += a*b0; acc[i][1] += a*b1; acc[i][2] += a*b2;
        }
    }
    #pragma unroll
    for (int i = 0; i < 4; i++)
        #pragma unroll
        for (int q = 0; q < 3; q++)
            g_T[(rowbase + r0 + i)*NJ + j0 + q] = acc[i][q];
}

// -------- forward stage 2: X[t,s] = sum_u e^{-i th_y} T[u,s], 2 s per thread --------
#define SM_F2 (2*256*48*4)
__global__ void k_f2() {
    extern __shared__ float sm[];
    float* sT  = sm;           // 12288
    float* sFy = sm + 12288;   // 12288
    int tx = threadIdx.x;      // 0..11 (s-pair)
    int ty = threadIdx.y;      // 0..23 (t)
    int tid = ty*12 + tx;
    size_t bc = blockIdx.x;
    const float4* Tp = (const float4*)(g_T + bc*Sn*NJ);
    for (int i = tid; i < 3072; i += 288) {
        ((float4*)sT)[i]  = Tp[i];
        ((float4*)sFy)[i] = ((const float4*)g_TFy)[i];
    }
    __syncthreads();
    float xr0=0.f, xi0=0.f, xr1=0.f, xi1=0.f;
    #pragma unroll 4
    for (int u = 0; u < 256; u++) {
        float2 ab = *(const float2*)(sFy + u*NJ + 2*ty);
        float4 tt = *(const float4*)(sT + u*NJ + 4*tx);
        xr0 += ab.x*tt.x - ab.y*tt.y;
        xi0 += ab.x*tt.y + ab.y*tt.x;
        xr1 += ab.x*tt.z - ab.y*tt.w;
        xi1 += ab.x*tt.w + ab.y*tt.z;
    }
    float4 o; o.x=xr0; o.y=xi0; o.z=xr1; o.w=xi1;
    *((float4*)(g_X + (bc*NM + ty*24 + 2*tx)*2)) = o;
}

// -------- per-mode complex channel mixing --------
__global__ void k_mix(int Cin) {
    __shared__ float sx[C0c*2];
    int mode = blockIdx.x; int b = blockIdx.y;
    int t = mode / 24, s = mode % 24;
    int q = (t >= 12 ? 1 : 0) + (s >= 12 ? 2 : 0);
    int m = (t % 12)*12 + (s % 12);
    int co = threadIdx.x;
    for (int i = co; i < Cin*2; i += 32)
        sx[i] = g_X[(((size_t)b*Cin + (i >> 1))*NM + mode)*2 + (i & 1)];
    __syncthreads();
    const float2* wp = (const float2*)g_wmix + (size_t)(q*144 + m)*Cin*WID;
    float orr = 0.f, oi = 0.f;
    for (int ci = 0; ci < Cin; ci++) {
        float2 w = wp[ci*WID + co];
        float xr = sx[2*ci], xi = sx[2*ci + 1];
        orr += xr*w.x - xi*w.y;
        oi  += xr*w.y + xi*w.x;
    }
    g_OF[(((size_t)b*WID + co)*NM + mode)*2]     = orr;
    g_OF[(((size_t)b*WID + co)*NM + mode)*2 + 1] = oi;
}

// -------- inverse stage 1: ky-iDFT (24 -> 256 rows), 48 accumulators/thread --------
#define SM_I1 ((1152 + 256*49)*4)
__global__ __launch_bounds__(256) void k_i1() {
    extern __shared__ float sm[];
    float* sOF = sm;            // 1152
    float* sGy = sm + 1152;     // 256 x 49 (padded)
    int tid = threadIdx.x;
    size_t bc = blockIdx.x;     // b*32 + co
    for (int i = tid; i < NM*2; i += 256) sOF[i] = g_OF[bc*NM*2 + i];
    for (int i = tid; i < Sn*NJ; i += 256) {
        int u = i / NJ, j = i % NJ;
        sGy[u*49 + j] = g_TGy[i];
    }
    __syncthreads();
    int u = tid;
    const float* grow = sGy + u*49;
    float ar[24], ai[24];
    #pragma unroll
    for (int s = 0; s < 24; s++) { ar[s] = 0.f; ai[s] = 0.f; }
    #pragma unroll 1
    for (int t = 0; t < 24; t++) {
        float C = grow[2*t], S = grow[2*t + 1];
        const float2* ofp = (const float2*)(sOF + t*48);
        #pragma unroll
        for (int s = 0; s < 24; s++) {
            float2 of = ofp[s];
            ar[s] += C*of.x - S*of.y;
            ai[s] += C*of.y + S*of.x;
        }
    }
    float4* gp = (float4*)(g_G + (bc*Sn + u)*NJ);
    #pragma unroll
    for (int s4 = 0; s4 < 12; s4++) {
        float4 o; o.x = ar[2*s4]; o.y = ai[2*s4]; o.z = ar[2*s4+1]; o.w = ai[2*s4+1];
        gp[s4] = o;
    }
}

// -------- inverse stage 2 + 1x1 conv + bias + (gelu); Wx row in registers --------
template<int CIN, bool DOGELU>
__global__ __launch_bounds__(256) void k_i2(const float* __restrict__ src, float* __restrict__ dst,
                     const float* __restrict__ cw, const float* __restrict__ cb) {
    __shared__ float sG[32*48];
    __shared__ float scw[32*36];   // padded rows (36) for LDS.128
    __shared__ float scb[32];
    int tid = threadIdx.x;
    int u = blockIdx.x, b = blockIdx.y;
    for (int i = tid; i < 32*12; i += 256) {
        int co = i/12, j4 = i%12;
        ((float4*)(sG + co*48))[j4] =
            ((const float4*)(g_G + (((size_t)b*WID + co)*Sn + u)*NJ))[j4];
    }
    for (int i = tid; i < 32*CIN; i += 256)
        scw[(i/CIN)*36 + (i%CIN)] = cw[i];
    if (tid < 32) scb[tid] = cb[tid];
    // per-thread Wx row direct from gmem (L1/L2-resident table) into registers
    float wreg[48];
    {
        const float4* wp = (const float4*)(g_TWx + tid*NJ);
        #pragma unroll
        for (int q = 0; q < 12; q++) {
            float4 vv = wp[q];
            wreg[4*q] = vv.x; wreg[4*q+1] = vv.y; wreg[4*q+2] = vv.z; wreg[4*q+3] = vv.w;
        }
    }
    float r[CIN];
    #pragma unroll
    for (int ci = 0; ci < CIN; ci++)
        r[ci] = src[(((size_t)b*CIN + ci)*Sn + u)*Sn + tid];
    __syncthreads();
    #pragma unroll 1
    for (int co = 0; co < 32; co++) {
        const float* gg = sG + co*48;
        const float* ww = scw + co*36;
        float a0 = scb[co], a1 = 0.f, a2 = 0.f, a3 = 0.f;
        #pragma unroll
        for (int j = 0; j < 48; j += 4) {
            a0 += gg[j]*wreg[j];     a1 += gg[j+1]*wreg[j+1];
            a2 += gg[j+2]*wreg[j+2]; a3 += gg[j+3]*wreg[j+3];
        }
        #pragma unroll
        for (int ci = 0; ci + 3 < CIN; ci += 4) {
            a0 += r[ci]*ww[ci];     a1 += r[ci+1]*ww[ci+1];
            a2 += r[ci+2]*ww[ci+2]; a3 += r[ci+3]*ww[ci+3];
        }
        if (CIN & 3) {
            #pragma unroll
            for (int ci = CIN & ~3; ci < CIN; ci++) a0 += r[ci]*ww[ci];
        }
        float acc = (a0 + a1) + (a2 + a3);
        if (DOGELU) acc = 0.5f*acc*(1.0f + erff(acc*0.70710678118654752f));
        dst[(((size_t)b*WID + co)*Sn + u)*Sn + tid] = acc;
    }
}

// -------- fused fc1 + gelu + fc2 (W1 transposed in smem) --------
__global__ __launch_bounds__(256) void k_fc12(const float* __restrict__ w1, const float* __restrict__ b1,
                       const float* __restrict__ w2, const float* __restrict__ b2,
                       float* __restrict__ out) {
    __shared__ float sW1t[128*32];   // [k][c]
    __shared__ float sW2[128];
    __shared__ float sB1[128];
    int tid = threadIdx.x;
    for (int i = tid; i < 4096; i += 256) {
        int c = i / 128, k = i % 128;
        sW1t[k*32 + c] = w1[i];
    }
    if (tid < 128) { sW2[tid] = w2[tid]; sB1[tid] = b1[tid]; }
    __syncthreads();
    int u = blockIdx.x, b = blockIdx.y, v = tid;
    float hv[32];
    #pragma unroll
    for (int c = 0; c < 32; c++)
        hv[c] = g_h0[(((size_t)b*WID + c)*Sn + u)*Sn + v];
    float o = b2[0];
    #pragma unroll 2
    for (int k = 0; k < 128; k++) {
        const float* wk = sW1t + k*32;
        float z0 = sB1[k], z1 = 0.f, z2 = 0.f, z3 = 0.f;
        #pragma unroll
        for (int c = 0; c < 32; c += 4) {
            z0 += hv[c]*wk[c];     z1 += hv[c+1]*wk[c+1];
            z2 += hv[c+2]*wk[c+2]; z3 += hv[c+3]*wk[c+3];
        }
        float z = (z0 + z1) + (z2 + z3);
        z = 0.5f*z*(1.0f + erff(z*0.70710678118654752f));
        o += z*sW2[k];
    }
    out[((size_t)b*Sn + u)*Sn + v] = o;
}

// -------- host --------
extern "C" void kernel_launch(void* const* d_in, const int* in_sizes, int n_in,
                              void* d_out, int out_size) {
    const float* x    = (const float*)d_in[0];
    const float* ap   = (const float*)d_in[1];
    const float* fc0w = (const float*)d_in[2];
    const float* fc0b = (const float*)d_in[3];
    const float* rb[4] = {(const float*)d_in[4], (const float*)d_in[5],
                          (const float*)d_in[6], (const float*)d_in[7]};
    const float* cw[4] = {(const float*)d_in[8],  (const float*)d_in[10],
                          (const float*)d_in[12], (const float*)d_in[14]};
    const float* cb[4] = {(const float*)d_in[9],  (const float*)d_in[11],
                          (const float*)d_in[13], (const float*)d_in[15]};
    const float* fc1w = (const float*)d_in[16];
    const float* fc1b = (const float*)d_in[17];
    const float* fc2w = (const float*)d_in[18];
    const float* fc2b = (const float*)d_in[19];
    float* out = (float*)d_out;

    float *h0, *h1;
    cudaGetSymbolAddress((void**)&h0, g_h0);
    cudaGetSymbolAddress((void**)&h1, g_h1);

    cudaFuncSetAttribute(k_f1, cudaFuncAttributeMaxDynamicSharedMemorySize, SM_F1);
    cudaFuncSetAttribute(k_f2, cudaFuncAttributeMaxDynamicSharedMemorySize, SM_F2);
    cudaFuncSetAttribute(k_i1, cudaFuncAttributeMaxDynamicSharedMemorySize, SM_I1);

    k_init<<<256, 48>>>();
    k_fc0<<<dim3(Sn, Bn), 256>>>(x, ap, fc0w, fc0b);

    float* bufs[5] = {h0, h1, h0, h1, h0};
    for (int blk = 0; blk < 4; blk++) {
        int Cin = (blk == 0) ? 33 : 32;
        k_wprep<<<1024, 256>>>(rb[blk], Cin);
        int nrows = Bn*Cin*Sn;
        k_f1<<<nrows/F1_ROWS, 512, SM_F1>>>(bufs[blk]);
        k_f2<<<Bn*Cin, dim3(12, 24), SM_F2>>>();
        k_mix<<<dim3(NM, Bn), 32>>>(Cin);
        k_i1<<<Bn*WID, 256, SM_I1>>>();
        if (blk == 0)
            k_i2<33,true><<<dim3(Sn, Bn), 256>>>(bufs[0], bufs[1], cw[0], cb[0]);
        else if (blk < 3)
            k_i2<32,true><<<dim3(Sn, Bn), 256>>>(bufs[blk], bufs[blk+1], cw[blk], cb[blk]);
        else
            k_i2<32,false><<<dim3(Sn, Bn), 256>>>(bufs[3], bufs[4], cw[3], cb[3]);
    }
    k_fc12<<<dim3(Sn, Bn), 256>>>(fc1w, fc1b, fc2w, fc2b, out);
}

// round 5
// speedup vs baseline: 1.1855x; 1.0348x over previous
#include <cuda_runtime.h>
#include <math.h>

#define Bn 8
#define Sn 256
#define TIN 10
#define WID 32
#define C0c 33
#define NT 24
#define NJ 48
#define NM 576

// -------- scratch (device globals; no allocation allowed) --------
__device__ float g_h0[(size_t)Bn*C0c*Sn*Sn];   // 69 MB (33-ch buffer)
__device__ float g_h1[(size_t)Bn*WID*Sn*Sn];   // 67 MB (32-ch buffer)
__device__ float g_T [(size_t)Bn*C0c*Sn*NJ];   // 13 MB
__device__ float g_X [(size_t)Bn*C0c*NM*2];
__device__ float g_OF[(size_t)Bn*WID*NM*2];
__device__ float g_G [(size_t)Bn*WID*Sn*NJ];
__device__ float g_wmix[(size_t)4*144*C0c*WID*2];
__device__ float g_TFx[Sn*NJ];
__device__ float g_TFy[Sn*NJ];
__device__ float g_TGy[Sn*NJ];
__device__ float g_TWx[Sn*NJ];

// -------- twiddle tables (exact via double sincospi) --------
__global__ void k_init() {
    int v = blockIdx.x; int j = threadIdx.x; int t = j >> 1; int im = j & 1;
    int kx = t < 12 ? t : 105 + t;   // 0..11, 117..128
    int ky = t < 12 ? t : 232 + t;   // 0..11, 244..255
    double s, c;
    sincospi(2.0 * kx * v / 256.0, &s, &c);
    g_TFx[v*NJ + j] = im ? (float)(-s) : (float)c;
    const double inv = 1.0 / 65536.0;
    double ar, bi;
    if (kx == 0)        { ar = inv;        bi = 0.0; }
    else if (kx == 128) { ar = c * inv;    bi = 0.0; }
    else                { ar = 2.0*c*inv;  bi = -2.0*s*inv; }
    g_TWx[v*NJ + j] = im ? (float)bi : (float)ar;
    sincospi(2.0 * ky * v / 256.0, &s, &c);
    g_TFy[v*NJ + j] = im ? (float)(-s) : (float)c;
    g_TGy[v*NJ + j] = im ? (float)s    : (float)c;
}

// -------- fc0 + grid concat + a_para concat + *a, to NCHW --------
__global__ void k_fc0(const float* __restrict__ x, const float* __restrict__ ap,
                      const float* __restrict__ w, const float* __restrict__ bias) {
    __shared__ float sw[12*32];
    __shared__ float sb[32];
    int tid = threadIdx.x;
    for (int i = tid; i < 384; i += 256) sw[i] = w[i];
    if (tid < 32)  sb[tid] = bias[tid];
    __syncthreads();
    int u = blockIdx.x, b = blockIdx.y, v = tid;
    const float* xp = x + (((size_t)b*Sn + u)*Sn + v)*TIN;
    float in[12];
    #pragma unroll
    for (int t = 0; t < 10; t++) in[t] = xp[t];
    in[10] = u * (1.0f/255.0f);
    in[11] = v * (1.0f/255.0f);
    float a = ap[((size_t)b*Sn + u)*Sn + v];
    float* hp = g_h0 + (size_t)b*C0c*Sn*Sn + (size_t)u*Sn + v;
    #pragma unroll 4
    for (int c = 0; c < 32; c++) {
        float acc = sb[c];
        #pragma unroll
        for (int t = 0; t < 12; t++) acc += in[t]*sw[t*32 + c];
        hp[(size_t)c*Sn*Sn] = acc * a;
    }
    hp[(size_t)32*Sn*Sn] = a * a;
}

// -------- repack rainbow weights: [4,Ci,Co,12,12,2] -> [q][m][ci][co][2] --------
__global__ void k_wprep(const float* __restrict__ rb, int Cin) {
    int total = 4*144*Cin*WID*2;
    for (int i = blockIdx.x*blockDim.x + threadIdx.x; i < total; i += gridDim.x*blockDim.x) {
        int r = i & 1; int tmp = i >> 1;
        int co = tmp % WID; tmp /= WID;
        int ci = tmp % Cin; tmp /= Cin;
        int m = tmp % 144;  int q = tmp / 144;
        int m1 = m / 12, m2 = m % 12;
        g_wmix[i] = rb[((((size_t)(q*Cin + ci)*WID + co)*12 + m1)*12 + m2)*2 + r];
    }
}

// -------- forward stage 1: T = h @ TFx; A from gmem regs, B in smem --------
// 256 threads, 128 rows/block; thread = 2 rows x 12 cols
#define SM_F1 (256*48*4)
__global__ __launch_bounds__(256) void k_f1(const float* __restrict__ src) {
    extern __shared__ float sB[];   // 256 x 48
    int tid = threadIdx.x;
    for (int i = tid; i < 3072; i += 256)
        ((float4*)sB)[i] = ((const float4*)g_TFx)[i];
    __syncthreads();
    size_t row0 = (size_t)blockIdx.x*128 + (tid >> 2);
    size_t row1 = row0 + 64;
    int j0 = (tid & 3) * 12;
    const float4* A0 = (const float4*)(src + row0*256);
    const float4* A1 = (const float4*)(src + row1*256);
    float acc0[12] = {}, acc1[12] = {};
    #pragma unroll 2
    for (int k4 = 0; k4 < 64; k4++) {
        float4 a0 = A0[k4], a1 = A1[k4];
        float av0[4] = {a0.x, a0.y, a0.z, a0.w};
        float av1[4] = {a1.x, a1.y, a1.z, a1.w};
        #pragma unroll
        for (int kk = 0; kk < 4; kk++) {
            const float4* bp = (const float4*)(sB + (k4*4 + kk)*48 + j0);
            float4 b0 = bp[0], b1 = bp[1], b2 = bp[2];
            float bb[12] = {b0.x,b0.y,b0.z,b0.w, b1.x,b1.y,b1.z,b1.w, b2.x,b2.y,b2.z,b2.w};
            float p0 = av0[kk], p1 = av1[kk];
            #pragma unroll
            for (int q = 0; q < 12; q++) {
                acc0[q] += p0*bb[q];
                acc1[q] += p1*bb[q];
            }
        }
    }
    float4* o0 = (float4*)(g_T + row0*48 + j0);
    float4* o1 = (float4*)(g_T + row1*48 + j0);
    #pragma unroll
    for (int q4 = 0; q4 < 3; q4++) {
        float4 v0, v1;
        v0.x = acc0[4*q4];   v0.y = acc0[4*q4+1]; v0.z = acc0[4*q4+2]; v0.w = acc0[4*q4+3];
        v1.x = acc1[4*q4];   v1.y = acc1[4*q4+1]; v1.z = acc1[4*q4+2]; v1.w = acc1[4*q4+3];
        o0[q4] = v0; o1[q4] = v1;
    }
}

// -------- forward stage 2: X[t,s] = sum_u e^{-i th_y} T[u,s], 2 s per thread --------
#define SM_F2 (2*256*48*4)
__global__ void k_f2() {
    extern __shared__ float sm[];
    float* sT  = sm;           // 12288
    float* sFy = sm + 12288;   // 12288
    int tx = threadIdx.x;      // 0..11 (s-pair)
    int ty = threadIdx.y;      // 0..23 (t)
    int tid = ty*12 + tx;
    size_t bc = blockIdx.x;
    const float4* Tp = (const float4*)(g_T + bc*Sn*NJ);
    for (int i = tid; i < 3072; i += 288) {
        ((float4*)sT)[i]  = Tp[i];
        ((float4*)sFy)[i] = ((const float4*)g_TFy)[i];
    }
    __syncthreads();
    float xr0=0.f, xi0=0.f, xr1=0.f, xi1=0.f;
    #pragma unroll 4
    for (int u = 0; u < 256; u++) {
        float2 ab = *(const float2*)(sFy + u*NJ + 2*ty);
        float4 tt = *(const float4*)(sT + u*NJ + 4*tx);
        xr0 += ab.x*tt.x - ab.y*tt.y;
        xi0 += ab.x*tt.y + ab.y*tt.x;
        xr1 += ab.x*tt.z - ab.y*tt.w;
        xi1 += ab.x*tt.w + ab.y*tt.z;
    }
    float4 o; o.x=xr0; o.y=xi0; o.z=xr1; o.w=xi1;
    *((float4*)(g_X + (bc*NM + ty*24 + 2*tx)*2)) = o;
}

// -------- per-mode complex channel mixing --------
__global__ void k_mix(int Cin) {
    __shared__ float sx[C0c*2];
    int mode = blockIdx.x; int b = blockIdx.y;
    int t = mode / 24, s = mode % 24;
    int q = (t >= 12 ? 1 : 0) + (s >= 12 ? 2 : 0);
    int m = (t % 12)*12 + (s % 12);
    int co = threadIdx.x;
    for (int i = co; i < Cin*2; i += 32)
        sx[i] = g_X[(((size_t)b*Cin + (i >> 1))*NM + mode)*2 + (i & 1)];
    __syncthreads();
    const float2* wp = (const float2*)g_wmix + (size_t)(q*144 + m)*Cin*WID;
    float orr = 0.f, oi = 0.f;
    for (int ci = 0; ci < Cin; ci++) {
        float2 w = wp[ci*WID + co];
        float xr = sx[2*ci], xi = sx[2*ci + 1];
        orr += xr*w.x - xi*w.y;
        oi  += xr*w.y + xi*w.x;
    }
    g_OF[(((size_t)b*WID + co)*NM + mode)*2]     = orr;
    g_OF[(((size_t)b*WID + co)*NM + mode)*2 + 1] = oi;
}

// -------- inverse stage 1: ky-iDFT (24 -> 256 rows), 48 accumulators/thread --------
#define SM_I1 ((1152 + 256*49)*4)
__global__ __launch_bounds__(256) void k_i1() {
    extern __shared__ float sm[];
    float* sOF = sm;            // 1152
    float* sGy = sm + 1152;     // 256 x 49 (padded)
    int tid = threadIdx.x;
    size_t bc = blockIdx.x;     // b*32 + co
    for (int i = tid; i < NM*2; i += 256) sOF[i] = g_OF[bc*NM*2 + i];
    for (int i = tid; i < Sn*NJ; i += 256) {
        int u = i / NJ, j = i % NJ;
        sGy[u*49 + j] = g_TGy[i];
    }
    __syncthreads();
    int u = tid;
    const float* grow = sGy + u*49;
    float ar[24], ai[24];
    #pragma unroll
    for (int s = 0; s < 24; s++) { ar[s] = 0.f; ai[s] = 0.f; }
    #pragma unroll 1
    for (int t = 0; t < 24; t++) {
        float C = grow[2*t], S = grow[2*t + 1];
        const float2* ofp = (const float2*)(sOF + t*48);
        #pragma unroll
        for (int s = 0; s < 24; s++) {
            float2 of = ofp[s];
            ar[s] += C*of.x - S*of.y;
            ai[s] += C*of.y + S*of.x;
        }
    }
    float4* gp = (float4*)(g_G + (bc*Sn + u)*NJ);
    #pragma unroll
    for (int s4 = 0; s4 < 12; s4++) {
        float4 o; o.x = ar[2*s4]; o.y = ai[2*s4]; o.z = ar[2*s4+1]; o.w = ai[2*s4+1];
        gp[s4] = o;
    }
}

// -------- inverse stage 2 + 1x1 conv + bias + (gelu); float4 LDS --------
template<int CIN, bool DOGELU>
__global__ __launch_bounds__(256) void k_i2(const float* __restrict__ src, float* __restrict__ dst,
                     const float* __restrict__ cw, const float* __restrict__ cb) {
    __shared__ float sG[32*48];
    __shared__ float scw[32*36];   // padded rows (36) for LDS.128
    __shared__ float scb[32];
    int tid = threadIdx.x;
    int u = blockIdx.x, b = blockIdx.y;
    for (int i = tid; i < 32*12; i += 256) {
        int co = i/12, j4 = i%12;
        ((float4*)(sG + co*48))[j4] =
            ((const float4*)(g_G + (((size_t)b*WID + co)*Sn + u)*NJ))[j4];
    }
    for (int i = tid; i < 32*CIN; i += 256)
        scw[(i/CIN)*36 + (i%CIN)] = cw[i];
    if (tid < 32) scb[tid] = cb[tid];
    // per-thread Wx row direct from gmem (L1/L2-resident table) into registers
    float4 wr[12];
    {
        const float4* wp = (const float4*)(g_TWx + tid*NJ);
        #pragma unroll
        for (int q = 0; q < 12; q++) wr[q] = wp[q];
    }
    float r[CIN];
    #pragma unroll
    for (int ci = 0; ci < CIN; ci++)
        r[ci] = src[(((size_t)b*CIN + ci)*Sn + u)*Sn + tid];
    __syncthreads();
    #pragma unroll 1
    for (int co = 0; co < 32; co++) {
        const float4* gg4 = (const float4*)(sG + co*48);
        const float4* ww4 = (const float4*)(scw + co*36);
        float a0 = scb[co], a1 = 0.f, a2 = 0.f, a3 = 0.f;
        #pragma unroll
        for (int j4 = 0; j4 < 12; j4++) {
            float4 g = gg4[j4];
            a0 += g.x*wr[j4].x; a1 += g.y*wr[j4].y;
            a2 += g.z*wr[j4].z; a3 += g.w*wr[j4].w;
        }
        #pragma unroll
        for (int c4 = 0; c4 < CIN/4; c4++) {
            float4 w = ww4[c4];
            a0 += r[4*c4]*w.x;   a1 += r[4*c4+1]*w.y;
            a2 += r[4*c4+2]*w.z; a3 += r[4*c4+3]*w.w;
        }
        if (CIN & 3) {
            #pragma unroll
            for (int ci = CIN & ~3; ci < CIN; ci++) a0 += r[ci]*scw[co*36 + ci];
        }
        float acc = (a0 + a1) + (a2 + a3);
        if (DOGELU) acc = 0.5f*acc*(1.0f + erff(acc*0.70710678118654752f));
        dst[(((size_t)b*WID + co)*Sn + u)*Sn + tid] = acc;
    }
}

// -------- fused fc1 + gelu + fc2 (W1 transposed in smem) --------
__global__ __launch_bounds__(256) void k_fc12(const float* __restrict__ w1, const float* __restrict__ b1,
                       const float* __restrict__ w2, const float* __restrict__ b2,
                       float* __restrict__ out) {
    __shared__ float sW1t[128*32];   // [k][c]
    __shared__ float sW2[128];
    __shared__ float sB1[128];
    int tid = threadIdx.x;
    for (int i = tid; i < 4096; i += 256) {
        int c = i / 128, k = i % 128;
        sW1t[k*32 + c] = w1[i];
    }
    if (tid < 128) { sW2[tid] = w2[tid]; sB1[tid] = b1[tid]; }
    __syncthreads();
    int u = blockIdx.x, b = blockIdx.y, v = tid;
    float hv[32];
    #pragma unroll
    for (int c = 0; c < 32; c++)
        hv[c] = g_h0[(((size_t)b*WID + c)*Sn + u)*Sn + v];
    float o = b2[0];
    #pragma unroll 2
    for (int k = 0; k < 128; k++) {
        const float4* wk = (const float4*)(sW1t + k*32);
        float z0 = sB1[k], z1 = 0.f, z2 = 0.f, z3 = 0.f;
        #pragma unroll
        for (int c4 = 0; c4 < 8; c4++) {
            float4 w = wk[c4];
            z0 += hv[4*c4]*w.x;   z1 += hv[4*c4+1]*w.y;
            z2 += hv[4*c4+2]*w.z; z3 += hv[4*c4+3]*w.w;
        }
        float z = (z0 + z1) + (z2 + z3);
        z = 0.5f*z*(1.0f + erff(z*0.70710678118654752f));
        o += z*sW2[k];
    }
    out[((size_t)b*Sn + u)*Sn + v] = o;
}

// -------- host --------
extern "C" void kernel_launch(void* const* d_in, const int* in_sizes, int n_in,
                              void* d_out, int out_size) {
    const float* x    = (const float*)d_in[0];
    const float* ap   = (const float*)d_in[1];
    const float* fc0w = (const float*)d_in[2];
    const float* fc0b = (const float*)d_in[3];
    const float* rb[4] = {(const float*)d_in[4], (const float*)d_in[5],
                          (const float*)d_in[6], (const float*)d_in[7]};
    const float* cw[4] = {(const float*)d_in[8],  (const float*)d_in[10],
                          (const float*)d_in[12], (const float*)d_in[14]};
    const float* cb[4] = {(const float*)d_in[9],  (const float*)d_in[11],
                          (const float*)d_in[13], (const float*)d_in[15]};
    const float* fc1w = (const float*)d_in[16];
    const float* fc1b = (const float*)d_in[17];
    const float* fc2w = (const float*)d_in[18];
    const float* fc2b = (const float*)d_in[19];
    float* out = (float*)d_out;

    float *h0, *h1;
    cudaGetSymbolAddress((void**)&h0, g_h0);
    cudaGetSymbolAddress((void**)&h1, g_h1);

    cudaFuncSetAttribute(k_f1, cudaFuncAttributeMaxDynamicSharedMemorySize, SM_F1);
    cudaFuncSetAttribute(k_f2, cudaFuncAttributeMaxDynamicSharedMemorySize, SM_F2);
    cudaFuncSetAttribute(k_i1, cudaFuncAttributeMaxDynamicSharedMemorySize, SM_I1);

    k_init<<<256, 48>>>();
    k_fc0<<<dim3(Sn, Bn), 256>>>(x, ap, fc0w, fc0b);

    float* bufs[5] = {h0, h1, h0, h1, h0};
    for (int blk = 0; blk < 4; blk++) {
        int Cin = (blk == 0) ? 33 : 32;
        k_wprep<<<1024, 256>>>(rb[blk], Cin);
        int nrows = Bn*Cin*Sn;
        k_f1<<<nrows/128, 256, SM_F1>>>(bufs[blk]);
        k_f2<<<Bn*Cin, dim3(12, 24), SM_F2>>>();
        k_mix<<<dim3(NM, Bn), 32>>>(Cin);
        k_i1<<<Bn*WID, 256, SM_I1>>>();
        if (blk == 0)
            k_i2<33,true><<<dim3(Sn, Bn), 256>>>(bufs[0], bufs[1], cw[0], cb[0]);
        else if (blk < 3)
            k_i2<32,true><<<dim3(Sn, Bn), 256>>>(bufs[blk], bufs[blk+1], cw[blk], cb[blk]);
        else
            k_i2<32,false><<<dim3(Sn, Bn), 256>>>(bufs[3], bufs[4], cw[3], cb[3]);
    }
    k_fc12<<<dim3(Sn, Bn), 256>>>(fc1w, fc1b, fc2w, fc2b, out);
}

// round 7
// speedup vs baseline: 1.2910x; 1.0890x over previous
#include <cuda_runtime.h>
#include <math.h>

#define Bn 8
#define Sn 256
#define TIN 10
#define WID 32
#define C0c 33
#define NT 24
#define NJ 48
#define NM 576
#define WSTRIDE (4*144*C0c*WID*2)

// -------- scratch (device globals; no allocation allowed) --------
__device__ float g_h0[(size_t)Bn*C0c*Sn*Sn];   // 69 MB
__device__ float g_h1[(size_t)Bn*WID*Sn*Sn];   // 67 MB
__device__ float g_T [(size_t)Bn*C0c*Sn*NJ];   // 13 MB (k-half 0)
__device__ float g_T2[(size_t)Bn*C0c*Sn*NJ];   // 13 MB (k-half 1)
__device__ float g_X [(size_t)Bn*C0c*NM*2];
__device__ float g_OF[(size_t)Bn*WID*NM*2];
__device__ float g_G [(size_t)Bn*WID*Sn*NJ];
__device__ float g_wmix[(size_t)4*WSTRIDE];
__device__ float g_TFx[Sn*NJ];
__device__ float g_TFy[Sn*NJ];
__device__ float g_TGy[Sn*NJ];
__device__ float g_TWx[Sn*NJ];

// -------- twiddle tables (exact via double sincospi) --------
__global__ void k_init() {
    int v = blockIdx.x; int j = threadIdx.x; int t = j >> 1; int im = j & 1;
    int kx = t < 12 ? t : 105 + t;
    int ky = t < 12 ? t : 232 + t;
    double s, c;
    sincospi(2.0 * kx * v / 256.0, &s, &c);
    g_TFx[v*NJ + j] = im ? (float)(-s) : (float)c;
    const double inv = 1.0 / 65536.0;
    double ar, bi;
    if (kx == 0)        { ar = inv;        bi = 0.0; }
    else if (kx == 128) { ar = c * inv;    bi = 0.0; }
    else                { ar = 2.0*c*inv;  bi = -2.0*s*inv; }
    g_TWx[v*NJ + j] = im ? (float)bi : (float)ar;
    sincospi(2.0 * ky * v / 256.0, &s, &c);
    g_TFy[v*NJ + j] = im ? (float)(-s) : (float)c;
    g_TGy[v*NJ + j] = im ? (float)s    : (float)c;
}

// -------- fc0 + grid concat + a_para concat + *a, to NCHW --------
__global__ void k_fc0(const float* __restrict__ x, const float* __restrict__ ap,
                      const float* __restrict__ w, const float* __restrict__ bias) {
    __shared__ float sw[12*32];
    __shared__ float sb[32];
    int tid = threadIdx.x;
    for (int i = tid; i < 384; i += 256) sw[i] = w[i];
    if (tid < 32)  sb[tid] = bias[tid];
    __syncthreads();
    int u = blockIdx.x, b = blockIdx.y, v = tid;
    const float* xp = x + (((size_t)b*Sn + u)*Sn + v)*TIN;
    float in[12];
    #pragma unroll
    for (int t = 0; t < 10; t++) in[t] = xp[t];
    in[10] = u * (1.0f/255.0f);
    in[11] = v * (1.0f/255.0f);
    float a = ap[((size_t)b*Sn + u)*Sn + v];
    float* hp = g_h0 + (size_t)b*C0c*Sn*Sn + (size_t)u*Sn + v;
    #pragma unroll 4
    for (int c = 0; c < 32; c++) {
        float acc = sb[c];
        #pragma unroll
        for (int t = 0; t < 12; t++) acc += in[t]*sw[t*32 + c];
        hp[(size_t)c*Sn*Sn] = acc * a;
    }
    hp[(size_t)32*Sn*Sn] = a * a;
}

// -------- repack rainbow weights for all 4 blocks in one launch --------
__global__ void k_wprep(const float* __restrict__ rb0, const float* __restrict__ rb1,
                        const float* __restrict__ rb2, const float* __restrict__ rb3) {
    int blk = blockIdx.y;
    const float* rb = blk == 0 ? rb0 : blk == 1 ? rb1 : blk == 2 ? rb2 : rb3;
    int Cin = blk == 0 ? C0c : WID;
    int total = 4*144*Cin*WID*2;
    float* wout = g_wmix + (size_t)blk*WSTRIDE;
    for (int i = blockIdx.x*blockDim.x + threadIdx.x; i < total; i += gridDim.x*blockDim.x) {
        int r = i & 1; int tmp = i >> 1;
        int co = tmp % WID; tmp /= WID;
        int ci = tmp % Cin; tmp /= Cin;
        int m = tmp % 144;  int q = tmp / 144;
        int m1 = m / 12, m2 = m % 12;
        wout[i] = rb[((((size_t)(q*Cin + ci)*WID + co)*12 + m1)*12 + m2)*2 + r];
    }
}

// -------- forward stage 1: T = h @ TFx, k-split halves, 4 rows x 12 cols/thread --------
__global__ __launch_bounds__(256) void k_f1(const float* __restrict__ src,
                                            float* __restrict__ d0, float* __restrict__ d1) {
    __shared__ float sB[128*48];   // half of the k-range of TFx
    int tid = threadIdx.x;
    int half = blockIdx.y;
    float* dst = half ? d1 : d0;
    for (int i = tid; i < 128*48/4; i += 256)
        ((float4*)sB)[i] = ((const float4*)(g_TFx + half*128*NJ))[i];
    __syncthreads();
    int jg = tid & 3, rowg = tid >> 2;                 // jg: 12-col group, rowg: 0..63
    size_t r0 = (size_t)blockIdx.x*256 + rowg*4;       // 4 consecutive rows
    int j0 = jg*12;
    // FIXED: half-row offset is 128 floats = 32 float4 (was 64 = a full row)
    const float4* A0 = (const float4*)(src + r0*256) + half*32;
    const float4* A1 = (const float4*)(src + (r0+1)*256) + half*32;
    const float4* A2 = (const float4*)(src + (r0+2)*256) + half*32;
    const float4* A3 = (const float4*)(src + (r0+3)*256) + half*32;
    float acc[4][12] = {};
    #pragma unroll 2
    for (int k4 = 0; k4 < 32; k4++) {
        float4 a0 = A0[k4], a1 = A1[k4], a2 = A2[k4], a3 = A3[k4];
        float av[4][4] = {{a0.x,a0.y,a0.z,a0.w},{a1.x,a1.y,a1.z,a1.w},
                          {a2.x,a2.y,a2.z,a2.w},{a3.x,a3.y,a3.z,a3.w}};
        #pragma unroll
        for (int kk = 0; kk < 4; kk++) {
            const float4* bp = (const float4*)(sB + (k4*4 + kk)*48 + j0);
            float4 b0 = bp[0], b1 = bp[1], b2 = bp[2];
            float bb[12] = {b0.x,b0.y,b0.z,b0.w, b1.x,b1.y,b1.z,b1.w, b2.x,b2.y,b2.z,b2.w};
            #pragma unroll
            for (int i = 0; i < 4; i++) {
                float p = av[i][kk];
                #pragma unroll
                for (int q = 0; q < 12; q++) acc[i][q] += p*bb[q];
            }
        }
    }
    #pragma unroll
    for (int i = 0; i < 4; i++) {
        float4* op = (float4*)(dst + (r0 + i)*NJ + j0);
        #pragma unroll
        for (int q4 = 0; q4 < 3; q4++) {
            float4 v;
            v.x = acc[i][4*q4]; v.y = acc[i][4*q4+1]; v.z = acc[i][4*q4+2]; v.w = acc[i][4*q4+3];
            op[q4] = v;
        }
    }
}

// -------- forward stage 2: sums k-halves on load; X[t,s] over 256 u --------
#define SM_F2 (2*256*48*4)
__global__ void k_f2() {
    extern __shared__ float sm[];
    float* sT  = sm;           // 12288
    float* sFy = sm + 12288;   // 12288
    int tx = threadIdx.x;      // 0..11 (s-pair)
    int ty = threadIdx.y;      // 0..23 (t)
    int tid = ty*12 + tx;
    size_t bc = blockIdx.x;
    const float4* Tp0 = (const float4*)(g_T  + bc*Sn*NJ);
    const float4* Tp1 = (const float4*)(g_T2 + bc*Sn*NJ);
    for (int i = tid; i < 3072; i += 288) {
        float4 a = Tp0[i], b = Tp1[i];
        float4 s; s.x = a.x+b.x; s.y = a.y+b.y; s.z = a.z+b.z; s.w = a.w+b.w;
        ((float4*)sT)[i]  = s;
        ((float4*)sFy)[i] = ((const float4*)g_TFy)[i];
    }
    __syncthreads();
    float xr0=0.f, xi0=0.f, xr1=0.f, xi1=0.f;
    #pragma unroll 4
    for (int u = 0; u < 256; u++) {
        float2 ab = *(const float2*)(sFy + u*NJ + 2*ty);
        float4 tt = *(const float4*)(sT + u*NJ + 4*tx);
        xr0 += ab.x*tt.x - ab.y*tt.y;
        xi0 += ab.x*tt.y + ab.y*tt.x;
        xr1 += ab.x*tt.z - ab.y*tt.w;
        xi1 += ab.x*tt.w + ab.y*tt.z;
    }
    float4 o; o.x=xr0; o.y=xi0; o.z=xr1; o.w=xi1;
    *((float4*)(g_X + (bc*NM + ty*24 + 2*tx)*2)) = o;
}

// -------- per-mode complex channel mixing --------
__global__ void k_mix(int Cin, int blk) {
    __shared__ float sx[C0c*2];
    int mode = blockIdx.x; int b = blockIdx.y;
    int t = mode / 24, s = mode % 24;
    int q = (t >= 12 ? 1 : 0) + (s >= 12 ? 2 : 0);
    int m = (t % 12)*12 + (s % 12);
    int co = threadIdx.x;
    for (int i = co; i < Cin*2; i += 32)
        sx[i] = g_X[(((size_t)b*Cin + (i >> 1))*NM + mode)*2 + (i & 1)];
    __syncthreads();
    const float2* wp = (const float2*)(g_wmix + (size_t)blk*WSTRIDE) + (size_t)(q*144 + m)*Cin*WID;
    float orr = 0.f, oi = 0.f;
    for (int ci = 0; ci < Cin; ci++) {
        float2 w = wp[ci*WID + co];
        float xr = sx[2*ci], xi = sx[2*ci + 1];
        orr += xr*w.x - xi*w.y;
        oi  += xr*w.y + xi*w.x;
    }
    g_OF[(((size_t)b*WID + co)*NM + mode)*2]     = orr;
    g_OF[(((size_t)b*WID + co)*NM + mode)*2 + 1] = oi;
}

// -------- inverse stage 1: ky-iDFT (24 -> 256 rows) --------
#define SM_I1 ((1152 + 256*49)*4)
__global__ __launch_bounds__(256) void k_i1() {
    extern __shared__ float sm[];
    float* sOF = sm;            // 1152
    float* sGy = sm + 1152;     // 256 x 49 (padded)
    int tid = threadIdx.x;
    size_t bc = blockIdx.x;     // b*32 + co
    for (int i = tid; i < NM*2; i += 256) sOF[i] = g_OF[bc*NM*2 + i];
    for (int i = tid; i < Sn*NJ; i += 256) {
        int u = i / NJ, j = i % NJ;
        sGy[u*49 + j] = g_TGy[i];
    }
    __syncthreads();
    int u = tid;
    const float* grow = sGy + u*49;
    float ar[24], ai[24];
    #pragma unroll
    for (int s = 0; s < 24; s++) { ar[s] = 0.f; ai[s] = 0.f; }
    #pragma unroll 1
    for (int t = 0; t < 24; t++) {
        float C = grow[2*t], S = grow[2*t + 1];
        const float2* ofp = (const float2*)(sOF + t*48);
        #pragma unroll
        for (int s = 0; s < 24; s++) {
            float2 of = ofp[s];
            ar[s] += C*of.x - S*of.y;
            ai[s] += C*of.y + S*of.x;
        }
    }
    float4* gp = (float4*)(g_G + (bc*Sn + u)*NJ);
    #pragma unroll
    for (int s4 = 0; s4 < 12; s4++) {
        float4 o; o.x = ar[2*s4]; o.y = ai[2*s4]; o.z = ar[2*s4+1]; o.w = ai[2*s4+1];
        gp[s4] = o;
    }
}

// -------- inverse stage 2 + 1x1 conv + bias + (gelu); co unrolled x2 --------
template<int CIN, bool DOGELU>
__global__ __launch_bounds__(256) void k_i2(const float* __restrict__ src, float* __restrict__ dst,
                     const float* __restrict__ cw, const float* __restrict__ cb) {
    __shared__ float sG[32*48];
    __shared__ float scw[32*36];
    __shared__ float scb[32];
    int tid = threadIdx.x;
    int u = blockIdx.x, b = blockIdx.y;
    for (int i = tid; i < 32*12; i += 256) {
        int co = i/12, j4 = i%12;
        ((float4*)(sG + co*48))[j4] =
            ((const float4*)(g_G + (((size_t)b*WID + co)*Sn + u)*NJ))[j4];
    }
    for (int i = tid; i < 32*CIN; i += 256)
        scw[(i/CIN)*36 + (i%CIN)] = cw[i];
    if (tid < 32) scb[tid] = cb[tid];
    float4 wr[12];
    {
        const float4* wp = (const float4*)(g_TWx + tid*NJ);
        #pragma unroll
        for (int q = 0; q < 12; q++) wr[q] = wp[q];
    }
    float r[CIN];
    #pragma unroll
    for (int ci = 0; ci < CIN; ci++)
        r[ci] = src[(((size_t)b*CIN + ci)*Sn + u)*Sn + tid];
    __syncthreads();
    #pragma unroll 1
    for (int co = 0; co < 32; co += 2) {
        const float4* gA = (const float4*)(sG + co*48);
        const float4* gB = (const float4*)(sG + (co+1)*48);
        const float4* wA = (const float4*)(scw + co*36);
        const float4* wB = (const float4*)(scw + (co+1)*36);
        float a0 = scb[co], a1 = 0.f, a2 = 0.f, a3 = 0.f;
        float b0 = scb[co+1], b1 = 0.f, b2 = 0.f, b3 = 0.f;
        #pragma unroll
        for (int j4 = 0; j4 < 12; j4++) {
            float4 ga = gA[j4], gb = gB[j4], w = wr[j4];
            a0 += ga.x*w.x; a1 += ga.y*w.y; a2 += ga.z*w.z; a3 += ga.w*w.w;
            b0 += gb.x*w.x; b1 += gb.y*w.y; b2 += gb.z*w.z; b3 += gb.w*w.w;
        }
        #pragma unroll
        for (int c4 = 0; c4 < CIN/4; c4++) {
            float4 wa = wA[c4], wb = wB[c4];
            float r0 = r[4*c4], r1 = r[4*c4+1], r2 = r[4*c4+2], r3 = r[4*c4+3];
            a0 += r0*wa.x; a1 += r1*wa.y; a2 += r2*wa.z; a3 += r3*wa.w;
            b0 += r0*wb.x; b1 += r1*wb.y; b2 += r2*wb.z; b3 += r3*wb.w;
        }
        if (CIN & 3) {
            #pragma unroll
            for (int ci = CIN & ~3; ci < CIN; ci++) {
                a0 += r[ci]*scw[co*36 + ci];
                b0 += r[ci]*scw[(co+1)*36 + ci];
            }
        }
        float accA = (a0 + a1) + (a2 + a3);
        float accB = (b0 + b1) + (b2 + b3);
        if (DOGELU) {
            accA = 0.5f*accA*(1.0f + erff(accA*0.70710678118654752f));
            accB = 0.5f*accB*(1.0f + erff(accB*0.70710678118654752f));
        }
        dst[(((size_t)b*WID + co)*Sn + u)*Sn + tid] = accA;
        dst[(((size_t)b*WID + co+1)*Sn + u)*Sn + tid] = accB;
    }
}

// -------- fused fc1 + gelu + fc2 (W1 transposed in smem) --------
__global__ __launch_bounds__(256) void k_fc12(const float* __restrict__ w1, const float* __restrict__ b1,
                       const float* __restrict__ w2, const float* __restrict__ b2,
                       float* __restrict__ out) {
    __shared__ float sW1t[128*32];   // [k][c]
    __shared__ float sW2[128];
    __shared__ float sB1[128];
    int tid = threadIdx.x;
    for (int i = tid; i < 4096; i += 256) {
        int c = i / 128, k = i % 128;
        sW1t[k*32 + c] = w1[i];
    }
    if (tid < 128) { sW2[tid] = w2[tid]; sB1[tid] = b1[tid]; }
    __syncthreads();
    int u = blockIdx.x, b = blockIdx.y, v = tid;
    float hv[32];
    #pragma unroll
    for (int c = 0; c < 32; c++)
        hv[c] = g_h0[(((size_t)b*WID + c)*Sn + u)*Sn + v];
    float o = b2[0];
    #pragma unroll 2
    for (int k = 0; k < 128; k++) {
        const float4* wk = (const float4*)(sW1t + k*32);
        float z0 = sB1[k], z1 = 0.f, z2 = 0.f, z3 = 0.f;
        #pragma unroll
        for (int c4 = 0; c4 < 8; c4++) {
            float4 w = wk[c4];
            z0 += hv[4*c4]*w.x;   z1 += hv[4*c4+1]*w.y;
            z2 += hv[4*c4+2]*w.z; z3 += hv[4*c4+3]*w.w;
        }
        float z = (z0 + z1) + (z2 + z3);
        z = 0.5f*z*(1.0f + erff(z*0.70710678118654752f));
        o += z*sW2[k];
    }
    out[((size_t)b*Sn + u)*Sn + v] = o;
}

// -------- host --------
extern "C" void kernel_launch(void* const* d_in, const int* in_sizes, int n_in,
                              void* d_out, int out_size) {
    const float* x    = (const float*)d_in[0];
    const float* ap   = (const float*)d_in[1];
    const float* fc0w = (const float*)d_in[2];
    const float* fc0b = (const float*)d_in[3];
    const float* rb[4] = {(const float*)d_in[4], (const float*)d_in[5],
                          (const float*)d_in[6], (const float*)d_in[7]};
    const float* cw[4] = {(const float*)d_in[8],  (const float*)d_in[10],
                          (const float*)d_in[12], (const float*)d_in[14]};
    const float* cb[4] = {(const float*)d_in[9],  (const float*)d_in[11],
                          (const float*)d_in[13], (const float*)d_in[15]};
    const float* fc1w = (const float*)d_in[16];
    const float* fc1b = (const float*)d_in[17];
    const float* fc2w = (const float*)d_in[18];
    const float* fc2b = (const float*)d_in[19];
    float* out = (float*)d_out;

    float *h0, *h1, *t0, *t1;
    cudaGetSymbolAddress((void**)&h0, g_h0);
    cudaGetSymbolAddress((void**)&h1, g_h1);
    cudaGetSymbolAddress((void**)&t0, g_T);
    cudaGetSymbolAddress((void**)&t1, g_T2);

    cudaFuncSetAttribute(k_f2, cudaFuncAttributeMaxDynamicSharedMemorySize, SM_F2);
    cudaFuncSetAttribute(k_i1, cudaFuncAttributeMaxDynamicSharedMemorySize, SM_I1);

    k_init<<<256, 48>>>();
    k_wprep<<<dim3(256, 4), 256>>>(rb[0], rb[1], rb[2], rb[3]);
    k_fc0<<<dim3(Sn, Bn), 256>>>(x, ap, fc0w, fc0b);

    float* bufs[5] = {h0, h1, h0, h1, h0};
    for (int blk = 0; blk < 4; blk++) {
        int Cin = (blk == 0) ? 33 : 32;
        int nrows = Bn*Cin*Sn;
        k_f1<<<dim3(nrows/256, 2), 256>>>(bufs[blk], t0, t1);
        k_f2<<<Bn*Cin, dim3(12, 24), SM_F2>>>();
        k_mix<<<dim3(NM, Bn), 32>>>(Cin, blk);
        k_i1<<<Bn*WID, 256, SM_I1>>>();
        if (blk == 0)
            k_i2<33,true><<<dim3(Sn, Bn), 256>>>(bufs[0], bufs[1], cw[0], cb[0]);
        else if (blk < 3)
            k_i2<32,true><<<dim3(Sn, Bn), 256>>>(bufs[blk], bufs[blk+1], cw[blk], cb[blk]);
        else
            k_i2<32,false><<<dim3(Sn, Bn), 256>>>(bufs[3], bufs[4], cw[3], cb[3]);
    }
    k_fc12<<<dim3(Sn, Bn), 256>>>(fc1w, fc1b, fc2w, fc2b, out);
}

// round 8
// speedup vs baseline: 1.3322x; 1.0319x over previous
#include <cuda_runtime.h>
#include <math.h>

#define Bn 8
#define Sn 256
#define TIN 10
#define WID 32
#define C0c 33
#define NT 24
#define NJ 48
#define NM 576
#define WSTRIDE (4*144*C0c*WID*2)

// -------- scratch (device globals; no allocation allowed) --------
__device__ float g_h0[(size_t)Bn*C0c*Sn*Sn];   // 69 MB
__device__ float g_h1[(size_t)Bn*WID*Sn*Sn];   // 67 MB
__device__ float g_T [(size_t)Bn*C0c*Sn*NJ];   // 13 MB (k-half 0)
__device__ float g_T2[(size_t)Bn*C0c*Sn*NJ];   // 13 MB (k-half 1)
__device__ float g_X [(size_t)Bn*C0c*NM*2];
__device__ float g_OF[(size_t)Bn*WID*NM*2];
__device__ float g_G [(size_t)Bn*WID*Sn*NJ];
__device__ float g_wmix[(size_t)4*WSTRIDE];
__device__ float g_TFx[Sn*NJ];
__device__ float g_TFy[Sn*NJ];
__device__ float g_TGy[Sn*NJ];
__device__ float g_TWx[Sn*NJ];

// -------- twiddle tables (exact via double sincospi) --------
__global__ void k_init() {
    int v = blockIdx.x; int j = threadIdx.x; int t = j >> 1; int im = j & 1;
    int kx = t < 12 ? t : 105 + t;
    int ky = t < 12 ? t : 232 + t;
    double s, c;
    sincospi(2.0 * kx * v / 256.0, &s, &c);
    g_TFx[v*NJ + j] = im ? (float)(-s) : (float)c;
    const double inv = 1.0 / 65536.0;
    double ar, bi;
    if (kx == 0)        { ar = inv;        bi = 0.0; }
    else if (kx == 128) { ar = c * inv;    bi = 0.0; }
    else                { ar = 2.0*c*inv;  bi = -2.0*s*inv; }
    g_TWx[v*NJ + j] = im ? (float)bi : (float)ar;
    sincospi(2.0 * ky * v / 256.0, &s, &c);
    g_TFy[v*NJ + j] = im ? (float)(-s) : (float)c;
    g_TGy[v*NJ + j] = im ? (float)s    : (float)c;
}

// -------- fc0 + grid concat + a_para concat + *a, to NCHW --------
__global__ void k_fc0(const float* __restrict__ x, const float* __restrict__ ap,
                      const float* __restrict__ w, const float* __restrict__ bias) {
    __shared__ float sw[12*32];
    __shared__ float sb[32];
    int tid = threadIdx.x;
    for (int i = tid; i < 384; i += 256) sw[i] = w[i];
    if (tid < 32)  sb[tid] = bias[tid];
    __syncthreads();
    int u = blockIdx.x, b = blockIdx.y, v = tid;
    const float* xp = x + (((size_t)b*Sn + u)*Sn + v)*TIN;
    float in[12];
    #pragma unroll
    for (int t = 0; t < 10; t++) in[t] = xp[t];
    in[10] = u * (1.0f/255.0f);
    in[11] = v * (1.0f/255.0f);
    float a = ap[((size_t)b*Sn + u)*Sn + v];
    float* hp = g_h0 + (size_t)b*C0c*Sn*Sn + (size_t)u*Sn + v;
    #pragma unroll 4
    for (int c = 0; c < 32; c++) {
        float acc = sb[c];
        #pragma unroll
        for (int t = 0; t < 12; t++) acc += in[t]*sw[t*32 + c];
        hp[(size_t)c*Sn*Sn] = acc * a;
    }
    hp[(size_t)32*Sn*Sn] = a * a;
}

// -------- repack rainbow weights for all 4 blocks in one launch --------
__global__ void k_wprep(const float* __restrict__ rb0, const float* __restrict__ rb1,
                        const float* __restrict__ rb2, const float* __restrict__ rb3) {
    int blk = blockIdx.y;
    const float* rb = blk == 0 ? rb0 : blk == 1 ? rb1 : blk == 2 ? rb2 : rb3;
    int Cin = blk == 0 ? C0c : WID;
    int total = 4*144*Cin*WID*2;
    float* wout = g_wmix + (size_t)blk*WSTRIDE;
    for (int i = blockIdx.x*blockDim.x + threadIdx.x; i < total; i += gridDim.x*blockDim.x) {
        int r = i & 1; int tmp = i >> 1;
        int co = tmp % WID; tmp /= WID;
        int ci = tmp % Cin; tmp /= Cin;
        int m = tmp % 144;  int q = tmp / 144;
        int m1 = m / 12, m2 = m % 12;
        wout[i] = rb[((((size_t)(q*Cin + ci)*WID + co)*12 + m1)*12 + m2)*2 + r];
    }
}

// -------- forward stage 1: T = h @ TFx, k-split halves, 4 rows x 12 cols/thread --------
__global__ __launch_bounds__(256) void k_f1(const float* __restrict__ src,
                                            float* __restrict__ d0, float* __restrict__ d1) {
    __shared__ float sB[128*48];   // half of the k-range of TFx
    int tid = threadIdx.x;
    int half = blockIdx.y;
    float* dst = half ? d1 : d0;
    for (int i = tid; i < 128*48/4; i += 256)
        ((float4*)sB)[i] = ((const float4*)(g_TFx + half*128*NJ))[i];
    __syncthreads();
    int jg = tid & 3, rowg = tid >> 2;
    size_t r0 = (size_t)blockIdx.x*256 + rowg*4;
    int j0 = jg*12;
    const float4* A0 = (const float4*)(src + r0*256) + half*32;
    const float4* A1 = (const float4*)(src + (r0+1)*256) + half*32;
    const float4* A2 = (const float4*)(src + (r0+2)*256) + half*32;
    const float4* A3 = (const float4*)(src + (r0+3)*256) + half*32;
    float acc[4][12] = {};
    #pragma unroll 2
    for (int k4 = 0; k4 < 32; k4++) {
        float4 a0 = A0[k4], a1 = A1[k4], a2 = A2[k4], a3 = A3[k4];
        float av[4][4] = {{a0.x,a0.y,a0.z,a0.w},{a1.x,a1.y,a1.z,a1.w},
                          {a2.x,a2.y,a2.z,a2.w},{a3.x,a3.y,a3.z,a3.w}};
        #pragma unroll
        for (int kk = 0; kk < 4; kk++) {
            const float4* bp = (const float4*)(sB + (k4*4 + kk)*48 + j0);
            float4 b0 = bp[0], b1 = bp[1], b2 = bp[2];
            float bb[12] = {b0.x,b0.y,b0.z,b0.w, b1.x,b1.y,b1.z,b1.w, b2.x,b2.y,b2.z,b2.w};
            #pragma unroll
            for (int i = 0; i < 4; i++) {
                float p = av[i][kk];
                #pragma unroll
                for (int q = 0; q < 12; q++) acc[i][q] += p*bb[q];
            }
        }
    }
    #pragma unroll
    for (int i = 0; i < 4; i++) {
        float4* op = (float4*)(dst + (r0 + i)*NJ + j0);
        #pragma unroll
        for (int q4 = 0; q4 < 3; q4++) {
            float4 v;
            v.x = acc[i][4*q4]; v.y = acc[i][4*q4+1]; v.z = acc[i][4*q4+2]; v.w = acc[i][4*q4+3];
            op[q4] = v;
        }
    }
}

// -------- forward stage 2: sums k-halves on load; 2t x 2s per thread --------
#define SM_F2 (2*256*48*4)
__global__ void k_f2() {
    extern __shared__ float sm[];
    float* sT  = sm;           // 12288
    float* sFy = sm + 12288;   // 12288
    int tx = threadIdx.x;      // 0..11 (s-pair)
    int ty = threadIdx.y;      // 0..11 (t and t+12)
    int tid = ty*12 + tx;      // 0..143
    size_t bc = blockIdx.x;
    const float4* Tp0 = (const float4*)(g_T  + bc*Sn*NJ);
    const float4* Tp1 = (const float4*)(g_T2 + bc*Sn*NJ);
    for (int i = tid; i < 3072; i += 144) {
        float4 a = Tp0[i], b = Tp1[i];
        float4 s; s.x = a.x+b.x; s.y = a.y+b.y; s.z = a.z+b.z; s.w = a.w+b.w;
        ((float4*)sT)[i]  = s;
        ((float4*)sFy)[i] = ((const float4*)g_TFy)[i];
    }
    __syncthreads();
    float p0=0.f,p1=0.f,p2=0.f,p3=0.f;      // t=ty
    float q0=0.f,q1=0.f,q2=0.f,q3=0.f;      // t=ty+12
    #pragma unroll 4
    for (int u = 0; u < 256; u++) {
        float2 aA = *(const float2*)(sFy + u*NJ + 2*ty);
        float2 aB = *(const float2*)(sFy + u*NJ + 2*(ty+12));
        float4 tt = *(const float4*)(sT + u*NJ + 4*tx);
        p0 += aA.x*tt.x - aA.y*tt.y;  p1 += aA.x*tt.y + aA.y*tt.x;
        p2 += aA.x*tt.z - aA.y*tt.w;  p3 += aA.x*tt.w + aA.y*tt.z;
        q0 += aB.x*tt.x - aB.y*tt.y;  q1 += aB.x*tt.y + aB.y*tt.x;
        q2 += aB.x*tt.z - aB.y*tt.w;  q3 += aB.x*tt.w + aB.y*tt.z;
    }
    float4 oA; oA.x=p0; oA.y=p1; oA.z=p2; oA.w=p3;
    float4 oB; oB.x=q0; oB.y=q1; oB.z=q2; oB.w=q3;
    *((float4*)(g_X + (bc*NM + ty*24 + 2*tx)*2))        = oA;
    *((float4*)(g_X + (bc*NM + (ty+12)*24 + 2*tx)*2))   = oB;
}

// -------- per-mode complex channel mixing: 4 modes per block --------
__global__ void k_mix(int Cin, int blk) {
    __shared__ float sx[4][C0c*2];
    int mode0 = blockIdx.x*4; int b = blockIdx.y;
    int tid = threadIdx.x;
    int sub = tid >> 5, co = tid & 31;
    for (int i = tid; i < 4*Cin*2; i += 128) {
        int ss = i / (Cin*2), ii = i % (Cin*2);
        sx[ss][ii] = g_X[(((size_t)b*Cin + (ii >> 1))*NM + mode0 + ss)*2 + (ii & 1)];
    }
    __syncthreads();
    int mode = mode0 + sub;
    int t = mode / 24, s = mode % 24;
    int q = (t >= 12 ? 1 : 0) + (s >= 12 ? 2 : 0);
    int m = (t % 12)*12 + (s % 12);
    const float2* wp = (const float2*)(g_wmix + (size_t)blk*WSTRIDE) + (size_t)(q*144 + m)*Cin*WID;
    float orr = 0.f, oi = 0.f;
    const float* xv = sx[sub];
    for (int ci = 0; ci < Cin; ci++) {
        float2 w = wp[ci*WID + co];
        float xr = xv[2*ci], xi = xv[2*ci + 1];
        orr += xr*w.x - xi*w.y;
        oi  += xr*w.y + xi*w.x;
    }
    g_OF[(((size_t)b*WID + co)*NM + mode)*2]     = orr;
    g_OF[(((size_t)b*WID + co)*NM + mode)*2 + 1] = oi;
}

// -------- inverse stage 1: ky-iDFT (24 -> 256 rows) --------
#define SM_I1 ((1152 + 256*49)*4)
__global__ __launch_bounds__(256) void k_i1() {
    extern __shared__ float sm[];
    float* sOF = sm;            // 1152
    float* sGy = sm + 1152;     // 256 x 49 (padded)
    int tid = threadIdx.x;
    size_t bc = blockIdx.x;     // b*32 + co
    for (int i = tid; i < NM*2; i += 256) sOF[i] = g_OF[bc*NM*2 + i];
    for (int i = tid; i < Sn*NJ; i += 256) {
        int u = i / NJ, j = i % NJ;
        sGy[u*49 + j] = g_TGy[i];
    }
    __syncthreads();
    int u = tid;
    const float* grow = sGy + u*49;
    float ar[24], ai[24];
    #pragma unroll
    for (int s = 0; s < 24; s++) { ar[s] = 0.f; ai[s] = 0.f; }
    #pragma unroll 1
    for (int t = 0; t < 24; t++) {
        float C = grow[2*t], S = grow[2*t + 1];
        const float2* ofp = (const float2*)(sOF + t*48);
        #pragma unroll
        for (int s = 0; s < 24; s++) {
            float2 of = ofp[s];
            ar[s] += C*of.x - S*of.y;
            ai[s] += C*of.y + S*of.x;
        }
    }
    float4* gp = (float4*)(g_G + (bc*Sn + u)*NJ);
    #pragma unroll
    for (int s4 = 0; s4 < 12; s4++) {
        float4 o; o.x = ar[2*s4]; o.y = ai[2*s4]; o.z = ar[2*s4+1]; o.w = ai[2*s4+1];
        gp[s4] = o;
    }
}

// -------- inverse stage 2 + 1x1 conv + bias + (gelu); co unrolled x2 --------
template<int CIN, bool DOGELU>
__global__ __launch_bounds__(256) void k_i2(const float* __restrict__ src, float* __restrict__ dst,
                     const float* __restrict__ cw, const float* __restrict__ cb) {
    __shared__ float sG[32*48];
    __shared__ float scw[32*36];
    __shared__ float scb[32];
    int tid = threadIdx.x;
    int u = blockIdx.x, b = blockIdx.y;
    for (int i = tid; i < 32*12; i += 256) {
        int co = i/12, j4 = i%12;
        ((float4*)(sG + co*48))[j4] =
            ((const float4*)(g_G + (((size_t)b*WID + co)*Sn + u)*NJ))[j4];
    }
    for (int i = tid; i < 32*CIN; i += 256)
        scw[(i/CIN)*36 + (i%CIN)] = cw[i];
    if (tid < 32) scb[tid] = cb[tid];
    float4 wr[12];
    {
        const float4* wp = (const float4*)(g_TWx + tid*NJ);
        #pragma unroll
        for (int q = 0; q < 12; q++) wr[q] = wp[q];
    }
    float r[CIN];
    #pragma unroll
    for (int ci = 0; ci < CIN; ci++)
        r[ci] = src[(((size_t)b*CIN + ci)*Sn + u)*Sn + tid];
    __syncthreads();
    #pragma unroll 1
    for (int co = 0; co < 32; co += 2) {
        const float4* gA = (const float4*)(sG + co*48);
        const float4* gB = (const float4*)(sG + (co+1)*48);
        const float4* wA = (const float4*)(scw + co*36);
        const float4* wB = (const float4*)(scw + (co+1)*36);
        float a0 = scb[co], a1 = 0.f, a2 = 0.f, a3 = 0.f;
        float b0 = scb[co+1], b1 = 0.f, b2 = 0.f, b3 = 0.f;
        #pragma unroll
        for (int j4 = 0; j4 < 12; j4++) {
            float4 ga = gA[j4], gb = gB[j4], w = wr[j4];
            a0 += ga.x*w.x; a1 += ga.y*w.y; a2 += ga.z*w.z; a3 += ga.w*w.w;
            b0 += gb.x*w.x; b1 += gb.y*w.y; b2 += gb.z*w.z; b3 += gb.w*w.w;
        }
        #pragma unroll
        for (int c4 = 0; c4 < CIN/4; c4++) {
            float4 wa = wA[c4], wb = wB[c4];
            float r0 = r[4*c4], r1 = r[4*c4+1], r2 = r[4*c4+2], r3 = r[4*c4+3];
            a0 += r0*wa.x; a1 += r1*wa.y; a2 += r2*wa.z; a3 += r3*wa.w;
            b0 += r0*wb.x; b1 += r1*wb.y; b2 += r2*wb.z; b3 += r3*wb.w;
        }
        if (CIN & 3) {
            #pragma unroll
            for (int ci = CIN & ~3; ci < CIN; ci++) {
                a0 += r[ci]*scw[co*36 + ci];
                b0 += r[ci]*scw[(co+1)*36 + ci];
            }
        }
        float accA = (a0 + a1) + (a2 + a3);
        float accB = (b0 + b1) + (b2 + b3);
        if (DOGELU) {
            accA = 0.5f*accA*(1.0f + erff(accA*0.70710678118654752f));
            accB = 0.5f*accB*(1.0f + erff(accB*0.70710678118654752f));
        }
        dst[(((size_t)b*WID + co)*Sn + u)*Sn + tid] = accA;
        dst[(((size_t)b*WID + co+1)*Sn + u)*Sn + tid] = accB;
    }
}

// -------- fused fc1 + gelu + fc2; 2 u-rows per block share W loads --------
__global__ __launch_bounds__(256) void k_fc12(const float* __restrict__ w1, const float* __restrict__ b1,
                       const float* __restrict__ w2, const float* __restrict__ b2,
                       float* __restrict__ out) {
    __shared__ float sW1t[128*32];   // [k][c]
    __shared__ float sW2[128];
    __shared__ float sB1[128];
    int tid = threadIdx.x;
    for (int i = tid; i < 4096; i += 256) {
        int c = i / 128, k = i % 128;
        sW1t[k*32 + c] = w1[i];
    }
    if (tid < 128) { sW2[tid] = w2[tid]; sB1[tid] = b1[tid]; }
    __syncthreads();
    int u0 = blockIdx.x*2, b = blockIdx.y, v = tid;
    float hv0[32], hv1[32];
    #pragma unroll
    for (int c = 0; c < 32; c++) {
        const float* hp = g_h0 + (((size_t)b*WID + c)*Sn + u0)*Sn + v;
        hv0[c] = hp[0];
        hv1[c] = hp[Sn];
    }
    float o0 = b2[0], o1 = b2[0];
    #pragma unroll 2
    for (int k = 0; k < 128; k++) {
        const float4* wk = (const float4*)(sW1t + k*32);
        float z0 = sB1[k], z1 = 0.f, z2 = 0.f, z3 = 0.f;
        float y0 = sB1[k], y1 = 0.f, y2 = 0.f, y3 = 0.f;
        #pragma unroll
        for (int c4 = 0; c4 < 8; c4++) {
            float4 w = wk[c4];
            z0 += hv0[4*c4]*w.x;   z1 += hv0[4*c4+1]*w.y;
            z2 += hv0[4*c4+2]*w.z; z3 += hv0[4*c4+3]*w.w;
            y0 += hv1[4*c4]*w.x;   y1 += hv1[4*c4+1]*w.y;
            y2 += hv1[4*c4+2]*w.z; y3 += hv1[4*c4+3]*w.w;
        }
        float z = (z0 + z1) + (z2 + z3);
        float y = (y0 + y1) + (y2 + y3);
        z = 0.5f*z*(1.0f + erff(z*0.70710678118654752f));
        y = 0.5f*y*(1.0f + erff(y*0.70710678118654752f));
        o0 += z*sW2[k];
        o1 += y*sW2[k];
    }
    out[((size_t)b*Sn + u0)*Sn + v]     = o0;
    out[((size_t)b*Sn + u0 + 1)*Sn + v] = o1;
}

// -------- host --------
extern "C" void kernel_launch(void* const* d_in, const int* in_sizes, int n_in,
                              void* d_out, int out_size) {
    const float* x    = (const float*)d_in[0];
    const float* ap   = (const float*)d_in[1];
    const float* fc0w = (const float*)d_in[2];
    const float* fc0b = (const float*)d_in[3];
    const float* rb[4] = {(const float*)d_in[4], (const float*)d_in[5],
                          (const float*)d_in[6], (const float*)d_in[7]};
    const float* cw[4] = {(const float*)d_in[8],  (const float*)d_in[10],
                          (const float*)d_in[12], (const float*)d_in[14]};
    const float* cb[4] = {(const float*)d_in[9],  (const float*)d_in[11],
                          (const float*)d_in[13], (const float*)d_in[15]};
    const float* fc1w = (const float*)d_in[16];
    const float* fc1b = (const float*)d_in[17];
    const float* fc2w = (const float*)d_in[18];
    const float* fc2b = (const float*)d_in[19];
    float* out = (float*)d_out;

    float *h0, *h1, *t0, *t1;
    cudaGetSymbolAddress((void**)&h0, g_h0);
    cudaGetSymbolAddress((void**)&h1, g_h1);
    cudaGetSymbolAddress((void**)&t0, g_T);
    cudaGetSymbolAddress((void**)&t1, g_T2);

    cudaFuncSetAttribute(k_f2, cudaFuncAttributeMaxDynamicSharedMemorySize, SM_F2);
    cudaFuncSetAttribute(k_i1, cudaFuncAttributeMaxDynamicSharedMemorySize, SM_I1);

    k_init<<<256, 48>>>();
    k_wprep<<<dim3(256, 4), 256>>>(rb[0], rb[1], rb[2], rb[3]);
    k_fc0<<<dim3(Sn, Bn), 256>>>(x, ap, fc0w, fc0b);

    float* bufs[5] = {h0, h1, h0, h1, h0};
    for (int blk = 0; blk < 4; blk++) {
        int Cin = (blk == 0) ? 33 : 32;
        int nrows = Bn*Cin*Sn;
        k_f1<<<dim3(nrows/256, 2), 256>>>(bufs[blk], t0, t1);
        k_f2<<<Bn*Cin, dim3(12, 12), SM_F2>>>();
        k_mix<<<dim3(NM/4, Bn), 128>>>(Cin, blk);
        k_i1<<<Bn*WID, 256, SM_I1>>>();
        if (blk == 0)
            k_i2<33,true><<<dim3(Sn, Bn), 256>>>(bufs[0], bufs[1], cw[0], cb[0]);
        else if (blk < 3)
            k_i2<32,true><<<dim3(Sn, Bn), 256>>>(bufs[blk], bufs[blk+1], cw[blk], cb[blk]);
        else
            k_i2<32,false><<<dim3(Sn, Bn), 256>>>(bufs[3], bufs[4], cw[3], cb[3]);
    }
    k_fc12<<<dim3(Sn/2, Bn), 256>>>(fc1w, fc1b, fc2w, fc2b, out);
}

// round 9
// speedup vs baseline: 1.3895x; 1.0430x over previous
#include <cuda_runtime.h>
#include <math.h>

#define Bn 8
#define Sn 256
#define TIN 10
#define WID 32
#define C0c 33
#define NT 24
#define NJ 48
#define NM 576
#define WSTRIDE (4*144*C0c*WID*2)

// -------- scratch (device globals; no allocation allowed) --------
__device__ float g_h0[(size_t)Bn*C0c*Sn*Sn];   // 69 MB
__device__ float g_h1[(size_t)Bn*WID*Sn*Sn];   // 67 MB
__device__ float g_X [(size_t)Bn*C0c*NM*2];
__device__ float g_OF[(size_t)Bn*WID*NM*2];
__device__ float g_G [(size_t)Bn*WID*Sn*NJ];
__device__ float g_wmix[(size_t)4*WSTRIDE];
__device__ float g_TFx[Sn*NJ];
__device__ float g_TFy[Sn*NJ];
__device__ float g_TGy[Sn*NJ];
__device__ float g_TWx[Sn*NJ];

// -------- twiddle tables (exact via double sincospi) --------
__global__ void k_init() {
    int v = blockIdx.x; int j = threadIdx.x; int t = j >> 1; int im = j & 1;
    int kx = t < 12 ? t : 105 + t;
    int ky = t < 12 ? t : 232 + t;
    double s, c;
    sincospi(2.0 * kx * v / 256.0, &s, &c);
    g_TFx[v*NJ + j] = im ? (float)(-s) : (float)c;
    const double inv = 1.0 / 65536.0;
    double ar, bi;
    if (kx == 0)        { ar = inv;        bi = 0.0; }
    else if (kx == 128) { ar = c * inv;    bi = 0.0; }
    else                { ar = 2.0*c*inv;  bi = -2.0*s*inv; }
    g_TWx[v*NJ + j] = im ? (float)bi : (float)ar;
    sincospi(2.0 * ky * v / 256.0, &s, &c);
    g_TFy[v*NJ + j] = im ? (float)(-s) : (float)c;
    g_TGy[v*NJ + j] = im ? (float)s    : (float)c;
}

// -------- fc0 + grid concat + a_para concat + *a, to NCHW --------
__global__ void k_fc0(const float* __restrict__ x, const float* __restrict__ ap,
                      const float* __restrict__ w, const float* __restrict__ bias) {
    __shared__ float sw[12*32];
    __shared__ float sb[32];
    int tid = threadIdx.x;
    for (int i = tid; i < 384; i += 256) sw[i] = w[i];
    if (tid < 32)  sb[tid] = bias[tid];
    __syncthreads();
    int u = blockIdx.x, b = blockIdx.y, v = tid;
    const float* xp = x + (((size_t)b*Sn + u)*Sn + v)*TIN;
    float in[12];
    #pragma unroll
    for (int t = 0; t < 10; t++) in[t] = xp[t];
    in[10] = u * (1.0f/255.0f);
    in[11] = v * (1.0f/255.0f);
    float a = ap[((size_t)b*Sn + u)*Sn + v];
    float* hp = g_h0 + (size_t)b*C0c*Sn*Sn + (size_t)u*Sn + v;
    #pragma unroll 4
    for (int c = 0; c < 32; c++) {
        float acc = sb[c];
        #pragma unroll
        for (int t = 0; t < 12; t++) acc += in[t]*sw[t*32 + c];
        hp[(size_t)c*Sn*Sn] = acc * a;
    }
    hp[(size_t)32*Sn*Sn] = a * a;
}

// -------- repack rainbow weights for all 4 blocks in one launch --------
__global__ void k_wprep(const float* __restrict__ rb0, const float* __restrict__ rb1,
                        const float* __restrict__ rb2, const float* __restrict__ rb3) {
    int blk = blockIdx.y;
    const float* rb = blk == 0 ? rb0 : blk == 1 ? rb1 : blk == 2 ? rb2 : rb3;
    int Cin = blk == 0 ? C0c : WID;
    int total = 4*144*Cin*WID*2;
    float* wout = g_wmix + (size_t)blk*WSTRIDE;
    for (int i = blockIdx.x*blockDim.x + threadIdx.x; i < total; i += gridDim.x*blockDim.x) {
        int r = i & 1; int tmp = i >> 1;
        int co = tmp % WID; tmp /= WID;
        int ci = tmp % Cin; tmp /= Cin;
        int m = tmp % 144;  int q = tmp / 144;
        int m1 = m / 12, m2 = m % 12;
        wout[i] = rb[((((size_t)(q*Cin + ci)*WID + co)*12 + m1)*12 + m2)*2 + r];
    }
}

// -------- fused forward: T = h @ TFx (in regs->smem), then X = Fy^T @ T --------
// one block per channel (b,c); 256 threads; smem: sT 48KB + sAux 48KB (B overlay / Fy)
#define SM_FF (2*256*48*4)
__global__ __launch_bounds__(256) void k_ff(const float* __restrict__ src) {
    extern __shared__ float sm[];
    float* sT   = sm;            // 256 x 48
    float* sAux = sm + 256*48;   // B half (128x48) during f1; Fy (256x48) during f2
    int tid = threadIdx.x;
    size_t bc = blockIdx.x;
    const float* Abase = src + bc*(size_t)Sn*Sn;   // this channel's 256x256 tile
    int jg = tid & 3, rowg = tid >> 2;   // rowg 0..63
    int r0 = rowg*4;
    int j0 = jg*12;
    float acc[4][12] = {};
    for (int half = 0; half < 2; half++) {
        __syncthreads();   // previous half's B reads complete before overwrite
        for (int i = tid; i < 128*48/4; i += 256)
            ((float4*)sAux)[i] = ((const float4*)(g_TFx + half*128*NJ))[i];
        __syncthreads();
        const float4* A0 = (const float4*)(Abase + (size_t)(r0+0)*256) + half*32;
        const float4* A1 = (const float4*)(Abase + (size_t)(r0+1)*256) + half*32;
        const float4* A2 = (const float4*)(Abase + (size_t)(r0+2)*256) + half*32;
        const float4* A3 = (const float4*)(Abase + (size_t)(r0+3)*256) + half*32;
        #pragma unroll 2
        for (int k4 = 0; k4 < 32; k4++) {
            float4 a0 = A0[k4], a1 = A1[k4], a2 = A2[k4], a3 = A3[k4];
            float av[4][4] = {{a0.x,a0.y,a0.z,a0.w},{a1.x,a1.y,a1.z,a1.w},
                              {a2.x,a2.y,a2.z,a2.w},{a3.x,a3.y,a3.z,a3.w}};
            #pragma unroll
            for (int kk = 0; kk < 4; kk++) {
                const float4* bp = (const float4*)(sAux + (k4*4 + kk)*48 + j0);
                float4 b0 = bp[0], b1 = bp[1], b2 = bp[2];
                float bb[12] = {b0.x,b0.y,b0.z,b0.w, b1.x,b1.y,b1.z,b1.w, b2.x,b2.y,b2.z,b2.w};
                #pragma unroll
                for (int i = 0; i < 4; i++) {
                    float p = av[i][kk];
                    #pragma unroll
                    for (int q = 0; q < 12; q++) acc[i][q] += p*bb[q];
                }
            }
        }
    }
    // stash T in smem
    #pragma unroll
    for (int i = 0; i < 4; i++) {
        float4* op = (float4*)(sT + (r0 + i)*48 + j0);
        #pragma unroll
        for (int q4 = 0; q4 < 3; q4++) {
            float4 v;
            v.x = acc[i][4*q4]; v.y = acc[i][4*q4+1]; v.z = acc[i][4*q4+2]; v.w = acc[i][4*q4+3];
            op[q4] = v;
        }
    }
    __syncthreads();   // all compute done (B reads finished), sT visible
    for (int i = tid; i < 3072; i += 256)
        ((float4*)sAux)[i] = ((const float4*)g_TFy)[i];
    __syncthreads();
    // f2 phase: 144 threads, each 2t x 2s
    if (tid < 144) {
        int tx = tid % 12, ty = tid / 12;   // tx: s-pair, ty: t and t+12
        float p0=0.f,p1=0.f,p2=0.f,p3=0.f;
        float q0=0.f,q1=0.f,q2=0.f,q3=0.f;
        #pragma unroll 4
        for (int u = 0; u < 256; u++) {
            float2 aA = *(const float2*)(sAux + u*NJ + 2*ty);
            float2 aB = *(const float2*)(sAux + u*NJ + 2*(ty+12));
            float4 tt = *(const float4*)(sT + u*NJ + 4*tx);
            p0 += aA.x*tt.x - aA.y*tt.y;  p1 += aA.x*tt.y + aA.y*tt.x;
            p2 += aA.x*tt.z - aA.y*tt.w;  p3 += aA.x*tt.w + aA.y*tt.z;
            q0 += aB.x*tt.x - aB.y*tt.y;  q1 += aB.x*tt.y + aB.y*tt.x;
            q2 += aB.x*tt.z - aB.y*tt.w;  q3 += aB.x*tt.w + aB.y*tt.z;
        }
        float4 oA; oA.x=p0; oA.y=p1; oA.z=p2; oA.w=p3;
        float4 oB; oB.x=q0; oB.y=q1; oB.z=q2; oB.w=q3;
        *((float4*)(g_X + (bc*NM + ty*24 + 2*tx)*2))      = oA;
        *((float4*)(g_X + (bc*NM + (ty+12)*24 + 2*tx)*2)) = oB;
    }
}

// -------- per-mode complex channel mixing: 4 modes per block --------
__global__ void k_mix(int Cin, int blk) {
    __shared__ float sx[4][C0c*2];
    int mode0 = blockIdx.x*4; int b = blockIdx.y;
    int tid = threadIdx.x;
    int sub = tid >> 5, co = tid & 31;
    for (int i = tid; i < 4*Cin*2; i += 128) {
        int ss = i / (Cin*2), ii = i % (Cin*2);
        sx[ss][ii] = g_X[(((size_t)b*Cin + (ii >> 1))*NM + mode0 + ss)*2 + (ii & 1)];
    }
    __syncthreads();
    int mode = mode0 + sub;
    int t = mode / 24, s = mode % 24;
    int q = (t >= 12 ? 1 : 0) + (s >= 12 ? 2 : 0);
    int m = (t % 12)*12 + (s % 12);
    const float2* wp = (const float2*)(g_wmix + (size_t)blk*WSTRIDE) + (size_t)(q*144 + m)*Cin*WID;
    float orr = 0.f, oi = 0.f;
    const float* xv = sx[sub];
    for (int ci = 0; ci < Cin; ci++) {
        float2 w = wp[ci*WID + co];
        float xr = xv[2*ci], xi = xv[2*ci + 1];
        orr += xr*w.x - xi*w.y;
        oi  += xr*w.y + xi*w.x;
    }
    g_OF[(((size_t)b*WID + co)*NM + mode)*2]     = orr;
    g_OF[(((size_t)b*WID + co)*NM + mode)*2 + 1] = oi;
}

// -------- inverse stage 1: ky-iDFT (24 -> 256 rows) --------
#define SM_I1 ((1152 + 256*49)*4)
__global__ __launch_bounds__(256) void k_i1() {
    extern __shared__ float sm[];
    float* sOF = sm;            // 1152
    float* sGy = sm + 1152;     // 256 x 49 (padded)
    int tid = threadIdx.x;
    size_t bc = blockIdx.x;     // b*32 + co
    for (int i = tid; i < NM*2; i += 256) sOF[i] = g_OF[bc*NM*2 + i];
    for (int i = tid; i < Sn*NJ; i += 256) {
        int u = i / NJ, j = i % NJ;
        sGy[u*49 + j] = g_TGy[i];
    }
    __syncthreads();
    int u = tid;
    const float* grow = sGy + u*49;
    float ar[24], ai[24];
    #pragma unroll
    for (int s = 0; s < 24; s++) { ar[s] = 0.f; ai[s] = 0.f; }
    #pragma unroll 1
    for (int t = 0; t < 24; t++) {
        float C = grow[2*t], S = grow[2*t + 1];
        const float2* ofp = (const float2*)(sOF + t*48);
        #pragma unroll
        for (int s = 0; s < 24; s++) {
            float2 of = ofp[s];
            ar[s] += C*of.x - S*of.y;
            ai[s] += C*of.y + S*of.x;
        }
    }
    float4* gp = (float4*)(g_G + (bc*Sn + u)*NJ);
    #pragma unroll
    for (int s4 = 0; s4 < 12; s4++) {
        float4 o; o.x = ar[2*s4]; o.y = ai[2*s4]; o.z = ar[2*s4+1]; o.w = ai[2*s4+1];
        gp[s4] = o;
    }
}

// -------- inverse stage 2 + 1x1 conv + bias + (gelu); co unrolled x2 --------
template<int CIN, bool DOGELU>
__global__ __launch_bounds__(256) void k_i2(const float* __restrict__ src, float* __restrict__ dst,
                     const float* __restrict__ cw, const float* __restrict__ cb) {
    __shared__ float sG[32*48];
    __shared__ float scw[32*36];
    __shared__ float scb[32];
    int tid = threadIdx.x;
    int u = blockIdx.x, b = blockIdx.y;
    for (int i = tid; i < 32*12; i += 256) {
        int co = i/12, j4 = i%12;
        ((float4*)(sG + co*48))[j4] =
            ((const float4*)(g_G + (((size_t)b*WID + co)*Sn + u)*NJ))[j4];
    }
    for (int i = tid; i < 32*CIN; i += 256)
        scw[(i/CIN)*36 + (i%CIN)] = cw[i];
    if (tid < 32) scb[tid] = cb[tid];
    float4 wr[12];
    {
        const float4* wp = (const float4*)(g_TWx + tid*NJ);
        #pragma unroll
        for (int q = 0; q < 12; q++) wr[q] = wp[q];
    }
    float r[CIN];
    #pragma unroll
    for (int ci = 0; ci < CIN; ci++)
        r[ci] = src[(((size_t)b*CIN + ci)*Sn + u)*Sn + tid];
    __syncthreads();
    #pragma unroll 1
    for (int co = 0; co < 32; co += 2) {
        const float4* gA = (const float4*)(sG + co*48);
        const float4* gB = (const float4*)(sG + (co+1)*48);
        const float4* wA = (const float4*)(scw + co*36);
        const float4* wB = (const float4*)(scw + (co+1)*36);
        float a0 = scb[co], a1 = 0.f, a2 = 0.f, a3 = 0.f;
        float b0 = scb[co+1], b1 = 0.f, b2 = 0.f, b3 = 0.f;
        #pragma unroll
        for (int j4 = 0; j4 < 12; j4++) {
            float4 ga = gA[j4], gb = gB[j4], w = wr[j4];
            a0 += ga.x*w.x; a1 += ga.y*w.y; a2 += ga.z*w.z; a3 += ga.w*w.w;
            b0 += gb.x*w.x; b1 += gb.y*w.y; b2 += gb.z*w.z; b3 += gb.w*w.w;
        }
        #pragma unroll
        for (int c4 = 0; c4 < CIN/4; c4++) {
            float4 wa = wA[c4], wb = wB[c4];
            float r0 = r[4*c4], r1 = r[4*c4+1], r2 = r[4*c4+2], r3 = r[4*c4+3];
            a0 += r0*wa.x; a1 += r1*wa.y; a2 += r2*wa.z; a3 += r3*wa.w;
            b0 += r0*wb.x; b1 += r1*wb.y; b2 += r2*wb.z; b3 += r3*wb.w;
        }
        if (CIN & 3) {
            #pragma unroll
            for (int ci = CIN & ~3; ci < CIN; ci++) {
                a0 += r[ci]*scw[co*36 + ci];
                b0 += r[ci]*scw[(co+1)*36 + ci];
            }
        }
        float accA = (a0 + a1) + (a2 + a3);
        float accB = (b0 + b1) + (b2 + b3);
        if (DOGELU) {
            accA = 0.5f*accA*(1.0f + erff(accA*0.70710678118654752f));
            accB = 0.5f*accB*(1.0f + erff(accB*0.70710678118654752f));
        }
        dst[(((size_t)b*WID + co)*Sn + u)*Sn + tid] = accA;
        dst[(((size_t)b*WID + co+1)*Sn + u)*Sn + tid] = accB;
    }
}

// -------- fused fc1 + gelu + fc2; 2 u-rows per block share W loads --------
__global__ __launch_bounds__(256) void k_fc12(const float* __restrict__ w1, const float* __restrict__ b1,
                       const float* __restrict__ w2, const float* __restrict__ b2,
                       float* __restrict__ out) {
    __shared__ float sW1t[128*32];   // [k][c]
    __shared__ float sW2[128];
    __shared__ float sB1[128];
    int tid = threadIdx.x;
    for (int i = tid; i < 4096; i += 256) {
        int c = i / 128, k = i % 128;
        sW1t[k*32 + c] = w1[i];
    }
    if (tid < 128) { sW2[tid] = w2[tid]; sB1[tid] = b1[tid]; }
    __syncthreads();
    int u0 = blockIdx.x*2, b = blockIdx.y, v = tid;
    float hv0[32], hv1[32];
    #pragma unroll
    for (int c = 0; c < 32; c++) {
        const float* hp = g_h0 + (((size_t)b*WID + c)*Sn + u0)*Sn + v;
        hv0[c] = hp[0];
        hv1[c] = hp[Sn];
    }
    float o0 = b2[0], o1 = b2[0];
    #pragma unroll 2
    for (int k = 0; k < 128; k++) {
        const float4* wk = (const float4*)(sW1t + k*32);
        float z0 = sB1[k], z1 = 0.f, z2 = 0.f, z3 = 0.f;
        float y0 = sB1[k], y1 = 0.f, y2 = 0.f, y3 = 0.f;
        #pragma unroll
        for (int c4 = 0; c4 < 8; c4++) {
            float4 w = wk[c4];
            z0 += hv0[4*c4]*w.x;   z1 += hv0[4*c4+1]*w.y;
            z2 += hv0[4*c4+2]*w.z; z3 += hv0[4*c4+3]*w.w;
            y0 += hv1[4*c4]*w.x;   y1 += hv1[4*c4+1]*w.y;
            y2 += hv1[4*c4+2]*w.z; y3 += hv1[4*c4+3]*w.w;
        }
        float z = (z0 + z1) + (z2 + z3);
        float y = (y0 + y1) + (y2 + y3);
        z = 0.5f*z*(1.0f + erff(z*0.70710678118654752f));
        y = 0.5f*y*(1.0f + erff(y*0.70710678118654752f));
        o0 += z*sW2[k];
        o1 += y*sW2[k];
    }
    out[((size_t)b*Sn + u0)*Sn + v]     = o0;
    out[((size_t)b*Sn + u0 + 1)*Sn + v] = o1;
}

// -------- host --------
extern "C" void kernel_launch(void* const* d_in, const int* in_sizes, int n_in,
                              void* d_out, int out_size) {
    const float* x    = (const float*)d_in[0];
    const float* ap   = (const float*)d_in[1];
    const float* fc0w = (const float*)d_in[2];
    const float* fc0b = (const float*)d_in[3];
    const float* rb[4] = {(const float*)d_in[4], (const float*)d_in[5],
                          (const float*)d_in[6], (const float*)d_in[7]};
    const float* cw[4] = {(const float*)d_in[8],  (const float*)d_in[10],
                          (const float*)d_in[12], (const float*)d_in[14]};
    const float* cb[4] = {(const float*)d_in[9],  (const float*)d_in[11],
                          (const float*)d_in[13], (const float*)d_in[15]};
    const float* fc1w = (const float*)d_in[16];
    const float* fc1b = (const float*)d_in[17];
    const float* fc2w = (const float*)d_in[18];
    const float* fc2b = (const float*)d_in[19];
    float* out = (float*)d_out;

    float *h0, *h1;
    cudaGetSymbolAddress((void**)&h0, g_h0);
    cudaGetSymbolAddress((void**)&h1, g_h1);

    cudaFuncSetAttribute(k_ff, cudaFuncAttributeMaxDynamicSharedMemorySize, SM_FF);
    cudaFuncSetAttribute(k_i1, cudaFuncAttributeMaxDynamicSharedMemorySize, SM_I1);

    k_init<<<256, 48>>>();
    k_wprep<<<dim3(256, 4), 256>>>(rb[0], rb[1], rb[2], rb[3]);
    k_fc0<<<dim3(Sn, Bn), 256>>>(x, ap, fc0w, fc0b);

    float* bufs[5] = {h0, h1, h0, h1, h0};
    for (int blk = 0; blk < 4; blk++) {
        int Cin = (blk == 0) ? 33 : 32;
        k_ff<<<Bn*Cin, 256, SM_FF>>>(bufs[blk]);
        k_mix<<<dim3(NM/4, Bn), 128>>>(Cin, blk);
        k_i1<<<Bn*WID, 256, SM_I1>>>();
        if (blk == 0)
            k_i2<33,true><<<dim3(Sn, Bn), 256>>>(bufs[0], bufs[1], cw[0], cb[0]);
        else if (blk < 3)
            k_i2<32,true><<<dim3(Sn, Bn), 256>>>(bufs[blk], bufs[blk+1], cw[blk], cb[blk]);
        else
            k_i2<32,false><<<dim3(Sn, Bn), 256>>>(bufs[3], bufs[4], cw[3], cb[3]);
    }
    k_fc12<<<dim3(Sn/2, Bn), 256>>>(fc1w, fc1b, fc2w, fc2b, out);
}